// round 1
// baseline (speedup 1.0000x reference)
#include <cuda_runtime.h>
#include <math.h>

#define NLAYERS 6
#define DMODEL  512
#define NHEADS  8
#define DHEAD   64
#define BATCH   4
#define SEQ     1024
#define TOKENS  (BATCH*SEQ)      // 4096
#define DFF     2048
#define LN_EPS  1e-5f

// ---------------- scratch (device globals; no allocation allowed) ----------------
__device__ __align__(16) float g_x  [TOKENS*DMODEL];
__device__ __align__(16) float g_q  [TOKENS*DMODEL];
__device__ __align__(16) float g_k  [TOKENS*DMODEL];
__device__ __align__(16) float g_v  [TOKENS*DMODEL];
__device__ __align__(16) float g_att[TOKENS*DMODEL];
__device__ __align__(16) float g_y  [TOKENS*DMODEL];
__device__ __align__(16) float g_h1 [TOKENS*DFF];
__device__ __align__(16) float g_sc [(size_t)BATCH*NHEADS*SEQ*SEQ]; // 128 MB

// ---------------- block reductions ----------------
__device__ __forceinline__ float block_sum(float v) {
    __shared__ float s[32];
    #pragma unroll
    for (int o = 16; o; o >>= 1) v += __shfl_xor_sync(0xffffffffu, v, o);
    int lane = threadIdx.x & 31, w = threadIdx.x >> 5;
    if (lane == 0) s[w] = v;
    __syncthreads();
    int nw = blockDim.x >> 5;
    v = (threadIdx.x < (unsigned)nw) ? s[threadIdx.x] : 0.f;
    if (w == 0) {
        #pragma unroll
        for (int o = 16; o; o >>= 1) v += __shfl_xor_sync(0xffffffffu, v, o);
        if (lane == 0) s[0] = v;
    }
    __syncthreads();
    v = s[0];
    __syncthreads();
    return v;
}

__device__ __forceinline__ float block_max(float v) {
    __shared__ float s[32];
    #pragma unroll
    for (int o = 16; o; o >>= 1) v = fmaxf(v, __shfl_xor_sync(0xffffffffu, v, o));
    int lane = threadIdx.x & 31, w = threadIdx.x >> 5;
    if (lane == 0) s[w] = v;
    __syncthreads();
    int nw = blockDim.x >> 5;
    v = (threadIdx.x < (unsigned)nw) ? s[threadIdx.x] : -3.402823466e38f;
    if (w == 0) {
        #pragma unroll
        for (int o = 16; o; o >>= 1) v = fmaxf(v, __shfl_xor_sync(0xffffffffu, v, o));
        if (lane == 0) s[0] = v;
    }
    __syncthreads();
    v = s[0];
    __syncthreads();
    return v;
}

// ---------------- embedding + positional encoding ----------------
__global__ void embed_k(const int* __restrict__ tok, const float* __restrict__ emb,
                        float* __restrict__ x) {
    long long row = blockIdx.x;            // token index in [0, 4096)
    int s = (int)(row & (SEQ - 1));
    int tk = tok[row];
    int t = threadIdx.x;                   // 128 threads, 4 dims each
    #pragma unroll
    for (int j = 0; j < 4; j++) {
        int i = t * 4 + j;
        float freq = (float)exp(-(double)i * (9.210340371976184 / (double)DMODEL));
        float ang = (float)s * freq;
        float pe = (i & 1) ? cosf(ang) : sinf(ang);
        x[row * DMODEL + i] = emb[(long long)tk * DMODEL + i] + pe;
    }
}

// ---------------- generic tiled GEMM ----------------
// C[m][n] = scale * sum_k A[m][k] * (NT ? B[n][k] : B[k][n])  (+ bias[n]) (relu?)
// Batched over gridDim.z: batch z decomposes to (zb, zh) = (z/nh, z%nh),
// with per-axis strides on A, B, C.
template<int BM, int BN, int BK, int TM, int TN, bool NT, bool RELU>
__global__ __launch_bounds__(256) void gemm_k(
    const float* __restrict__ A, int lda, long long sAb, long long sAh,
    const float* __restrict__ B, int ldb, long long sBb, long long sBh,
    float* __restrict__ C, int ldc, long long sCb, long long sCh,
    const float* __restrict__ bias, float scale, int K, int nh)
{
    __shared__ float As[BK][BM + 4];
    __shared__ float Bs[BK][BN + 4];

    int z = blockIdx.z;
    int zb = z / nh, zh = z - zb * nh;
    A += zb * sAb + zh * sAh;
    B += zb * sBb + zh * sBh;
    C += zb * sCb + zh * sCh;

    const int m0 = blockIdx.y * BM;
    const int n0 = blockIdx.x * BN;
    const int t = threadIdx.x;

    // A (and NT-B) loader: one float4 per thread, BM*BK == 1024
    const int aRow = t / (BK / 4);
    const int aK   = (t % (BK / 4)) * 4;
    // NN-B loader: BK*BN == 1024
    const int bRow = t / (BN / 4);
    const int bCol = (t % (BN / 4)) * 4;

    const int tx = t % (BN / TN);
    const int ty = t / (BN / TN);

    float acc[TM][TN];
    #pragma unroll
    for (int i = 0; i < TM; i++)
        #pragma unroll
        for (int j = 0; j < TN; j++) acc[i][j] = 0.f;

    for (int k0 = 0; k0 < K; k0 += BK) {
        float4 av = *(const float4*)(A + (long long)(m0 + aRow) * lda + (k0 + aK));
        As[aK + 0][aRow] = av.x; As[aK + 1][aRow] = av.y;
        As[aK + 2][aRow] = av.z; As[aK + 3][aRow] = av.w;
        if (NT) {
            float4 bv = *(const float4*)(B + (long long)(n0 + aRow) * ldb + (k0 + aK));
            Bs[aK + 0][aRow] = bv.x; Bs[aK + 1][aRow] = bv.y;
            Bs[aK + 2][aRow] = bv.z; Bs[aK + 3][aRow] = bv.w;
        } else {
            float4 bv = *(const float4*)(B + (long long)(k0 + bRow) * ldb + (n0 + bCol));
            *(float4*)&Bs[bRow][bCol] = bv;
        }
        __syncthreads();
        #pragma unroll
        for (int kk = 0; kk < BK; kk++) {
            float a[TM], b[TN];
            #pragma unroll
            for (int i = 0; i < TM / 4; i++)
                *(float4*)&a[i * 4] = *(const float4*)&As[kk][ty * TM + i * 4];
            #pragma unroll
            for (int j = 0; j < TN / 4; j++)
                *(float4*)&b[j * 4] = *(const float4*)&Bs[kk][tx * TN + j * 4];
            #pragma unroll
            for (int i = 0; i < TM; i++)
                #pragma unroll
                for (int j = 0; j < TN; j++)
                    acc[i][j] = fmaf(a[i], b[j], acc[i][j]);
        }
        __syncthreads();
    }

    #pragma unroll
    for (int i = 0; i < TM; i++) {
        long long m = m0 + ty * TM + i;
        #pragma unroll
        for (int j4 = 0; j4 < TN / 4; j4++) {
            int n = n0 + tx * TN + j4 * 4;
            float4 o;
            float* ov = &o.x;
            #pragma unroll
            for (int j = 0; j < 4; j++) {
                float vv = acc[i][j4 * 4 + j] * scale;
                if (bias) vv += bias[n + j];
                if (RELU) vv = fmaxf(vv, 0.f);
                ov[j] = vv;
            }
            *(float4*)(C + m * ldc + n) = o;
        }
    }
}

// ---------------- softmax over rows of 1024 ----------------
__global__ void softmax_k(float* __restrict__ sc) {
    long long row = blockIdx.x;          // 32768 rows
    float* p = sc + row * SEQ;
    int t = threadIdx.x;                 // 256 threads * 4
    float4 v = *(float4*)(p + t * 4);
    float mx = block_max(fmaxf(fmaxf(v.x, v.y), fmaxf(v.z, v.w)));
    v.x = expf(v.x - mx); v.y = expf(v.y - mx);
    v.z = expf(v.z - mx); v.w = expf(v.w - mx);
    float s = block_sum(v.x + v.y + v.z + v.w);
    float inv = 1.f / s;
    v.x *= inv; v.y *= inv; v.z *= inv; v.w *= inv;
    *(float4*)(p + t * 4) = v;
}

// ---------------- fused residual add + LayerNorm ----------------
__global__ void addln_k(const float* __restrict__ a, const float* __restrict__ b,
                        const float* __restrict__ g, const float* __restrict__ be,
                        float* __restrict__ o) {
    long long row = blockIdx.x;          // 4096 rows of 512
    int t = threadIdx.x;                 // 128 threads * 4
    float4 av = *(const float4*)(a + row * DMODEL + t * 4);
    float4 bv = *(const float4*)(b + row * DMODEL + t * 4);
    float x0 = av.x + bv.x, x1 = av.y + bv.y, x2 = av.z + bv.z, x3 = av.w + bv.w;
    float m = block_sum(x0 + x1 + x2 + x3) * (1.f / DMODEL);
    float d0 = x0 - m, d1 = x1 - m, d2 = x2 - m, d3 = x3 - m;
    float var = block_sum(d0 * d0 + d1 * d1 + d2 * d2 + d3 * d3) * (1.f / DMODEL);
    float r = rsqrtf(var + LN_EPS);
    float4 gv = *(const float4*)(g + t * 4);
    float4 ev = *(const float4*)(be + t * 4);
    float4 ov;
    ov.x = d0 * r * gv.x + ev.x;
    ov.y = d1 * r * gv.y + ev.y;
    ov.z = d2 * r * gv.z + ev.z;
    ov.w = d3 * r * gv.w + ev.w;
    *(float4*)(o + row * DMODEL + t * 4) = ov;
}

// ---------------- launch ----------------
extern "C" void kernel_launch(void* const* d_in, const int* in_sizes, int n_in,
                              void* d_out, int out_size)
{
    const int*   tok = (const int*)d_in[0];
    const float* emb = (const float*)d_in[1];
    const float* Wq = (const float*)d_in[2],  *bq = (const float*)d_in[3];
    const float* Wk = (const float*)d_in[4],  *bk = (const float*)d_in[5];
    const float* Wv = (const float*)d_in[6],  *bv = (const float*)d_in[7];
    const float* Wo = (const float*)d_in[8],  *bo = (const float*)d_in[9];
    const float* W1 = (const float*)d_in[10], *b1 = (const float*)d_in[11];
    const float* W2 = (const float*)d_in[12], *b2 = (const float*)d_in[13];
    const float* lg = (const float*)d_in[14], *lb = (const float*)d_in[15];
    float* out = (float*)d_out;

    float *x, *qb, *kb, *vb, *att, *y, *h1, *sc;
    cudaGetSymbolAddress((void**)&x,   g_x);
    cudaGetSymbolAddress((void**)&qb,  g_q);
    cudaGetSymbolAddress((void**)&kb,  g_k);
    cudaGetSymbolAddress((void**)&vb,  g_v);
    cudaGetSymbolAddress((void**)&att, g_att);
    cudaGetSymbolAddress((void**)&y,   g_y);
    cudaGetSymbolAddress((void**)&h1,  g_h1);
    cudaGetSymbolAddress((void**)&sc,  g_sc);

    embed_k<<<TOKENS, 128>>>(tok, emb, x);

    const long long SDB = (long long)SEQ * DMODEL;     // 524288: per-batch stride in q/k/v
    const long long SCB = (long long)NHEADS * SEQ * SEQ; // 8388608: per-batch stride in scores
    const long long SCH = (long long)SEQ * SEQ;          // 1048576

    for (int i = 0; i < NLAYERS; i++) {
        const float* wq = Wq + (long long)i * DMODEL * DMODEL;
        const float* wk = Wk + (long long)i * DMODEL * DMODEL;
        const float* wv = Wv + (long long)i * DMODEL * DMODEL;
        const float* wo = Wo + (long long)i * DMODEL * DMODEL;
        const float* w1 = W1 + (long long)i * DMODEL * DFF;
        const float* w2 = W2 + (long long)i * DFF * DMODEL;
        const float* bqi = bq + (long long)i * DMODEL;
        const float* bki = bk + (long long)i * DMODEL;
        const float* bvi = bv + (long long)i * DMODEL;
        const float* boi = bo + (long long)i * DMODEL;
        const float* b1i = b1 + (long long)i * DFF;
        const float* b2i = b2 + (long long)i * DMODEL;
        const float* lgi = lg + (long long)i * DMODEL;
        const float* lbi = lb + (long long)i * DMODEL;

        // Q/K/V projections: [4096,512] @ [512,512] + bias
        gemm_k<128,128,8,8,8,false,false><<<dim3(4,32,1),256>>>(
            x,DMODEL,0,0, wq,DMODEL,0,0, qb,DMODEL,0,0, bqi,1.f,DMODEL,1);
        gemm_k<128,128,8,8,8,false,false><<<dim3(4,32,1),256>>>(
            x,DMODEL,0,0, wk,DMODEL,0,0, kb,DMODEL,0,0, bki,1.f,DMODEL,1);
        gemm_k<128,128,8,8,8,false,false><<<dim3(4,32,1),256>>>(
            x,DMODEL,0,0, wv,DMODEL,0,0, vb,DMODEL,0,0, bvi,1.f,DMODEL,1);

        // scores[bh] = (q @ k^T) / 8 : batched NT, M=N=1024, K=64
        gemm_k<128,128,8,8,8,true,false><<<dim3(8,8,BATCH*NHEADS),256>>>(
            qb,DMODEL,SDB,DHEAD, kb,DMODEL,SDB,DHEAD,
            sc,SEQ,SCB,SCH, nullptr,0.125f,DHEAD,NHEADS);

        softmax_k<<<BATCH*NHEADS*SEQ, 256>>>(sc);

        // attn[bh] = w @ v : batched NN, M=1024, N=64, K=1024,
        // output written [b][h][s][d] contiguous -> replicates reference reshape bug
        gemm_k<64,64,16,4,4,false,false><<<dim3(1,16,BATCH*NHEADS),256>>>(
            sc,SEQ,SCB,SCH, vb,DMODEL,SDB,DHEAD,
            att,DHEAD,SDB,(long long)SEQ*DHEAD, nullptr,1.f,SEQ,NHEADS);

        // O projection on the (bugged-layout) attention output viewed [4096,512]
        gemm_k<128,128,8,8,8,false,false><<<dim3(4,32,1),256>>>(
            att,DMODEL,0,0, wo,DMODEL,0,0, y,DMODEL,0,0, boi,1.f,DMODEL,1);

        addln_k<<<TOKENS,128>>>(x, y, lgi, lbi, x);

        // FFN
        gemm_k<128,128,8,8,8,false,true><<<dim3(16,32,1),256>>>(
            x,DMODEL,0,0, w1,DFF,0,0, h1,DFF,0,0, b1i,1.f,DMODEL,1);
        gemm_k<128,128,8,8,8,false,false><<<dim3(4,32,1),256>>>(
            h1,DFF,0,0, w2,DMODEL,0,0, y,DMODEL,0,0, b2i,1.f,DFF,1);

        addln_k<<<TOKENS,128>>>(x, y, lgi, lbi, (i == NLAYERS - 1) ? out : x);
    }
}

// round 3
// speedup vs baseline: 3.3367x; 3.3367x over previous
#include <cuda_runtime.h>
#include <cuda_bf16.h>
#include <math.h>
#include <cstdint>

#define NLAYERS 6
#define DMODEL  512
#define NHEADS  8
#define DHEAD   64
#define BATCH   4
#define SEQ     1024
#define TOKENS  (BATCH*SEQ)      // 4096
#define DFF     2048
#define LN_EPS  1e-5f

typedef __nv_bfloat16 bf16;

// ---------------- scratch (device globals; no allocation allowed) ----------------
__device__ __align__(16) float g_x  [TOKENS*DMODEL];
__device__ __align__(16) float g_y  [TOKENS*DMODEL];
__device__ __align__(16) float g_sc [(size_t)BATCH*NHEADS*SEQ*SEQ]; // 134 MB fp32 scores

__device__ __align__(16) bf16 g_xh[TOKENS*DMODEL],  g_xl[TOKENS*DMODEL];
__device__ __align__(16) bf16 g_qh[TOKENS*DMODEL],  g_ql[TOKENS*DMODEL];
__device__ __align__(16) bf16 g_kh[TOKENS*DMODEL],  g_kl[TOKENS*DMODEL];
__device__ __align__(16) bf16 g_vTh[TOKENS*DMODEL], g_vTl[TOKENS*DMODEL];   // [512][4096]
__device__ __align__(16) bf16 g_ah[TOKENS*DMODEL],  g_al[TOKENS*DMODEL];
__device__ __align__(16) bf16 g_h1h[TOKENS*DFF],    g_h1l[TOKENS*DFF];
__device__ __align__(16) bf16 g_ph[(size_t)BATCH*NHEADS*SEQ*SEQ], g_pl[(size_t)BATCH*NHEADS*SEQ*SEQ];

// transposed bf16 weights (all layers)
__device__ __align__(16) bf16 g_wqTh[NLAYERS*DMODEL*DMODEL], g_wqTl[NLAYERS*DMODEL*DMODEL];
__device__ __align__(16) bf16 g_wkTh[NLAYERS*DMODEL*DMODEL], g_wkTl[NLAYERS*DMODEL*DMODEL];
__device__ __align__(16) bf16 g_wvTh[NLAYERS*DMODEL*DMODEL], g_wvTl[NLAYERS*DMODEL*DMODEL];
__device__ __align__(16) bf16 g_woTh[NLAYERS*DMODEL*DMODEL], g_woTl[NLAYERS*DMODEL*DMODEL];
__device__ __align__(16) bf16 g_w1Th[NLAYERS*DMODEL*DFF],    g_w1Tl[NLAYERS*DMODEL*DFF];
__device__ __align__(16) bf16 g_w2Th[NLAYERS*DMODEL*DFF],    g_w2Tl[NLAYERS*DMODEL*DFF];

// ---------------- helpers ----------------
__device__ __forceinline__ void split_bf16(float v, bf16& h, bf16& l) {
    h = __float2bfloat16_rn(v);
    l = __float2bfloat16_rn(v - __bfloat162float(h));
}

__device__ __forceinline__ void cpasync16(unsigned saddr, const void* g) {
    asm volatile("cp.async.cg.shared.global [%0], [%1], 16;\n" :: "r"(saddr), "l"(g));
}

__device__ __forceinline__ float block_sum(float v) {
    __shared__ float s[32];
    #pragma unroll
    for (int o = 16; o; o >>= 1) v += __shfl_xor_sync(0xffffffffu, v, o);
    int lane = threadIdx.x & 31, w = threadIdx.x >> 5;
    if (lane == 0) s[w] = v;
    __syncthreads();
    int nw = blockDim.x >> 5;
    v = (threadIdx.x < (unsigned)nw) ? s[threadIdx.x] : 0.f;
    if (w == 0) {
        #pragma unroll
        for (int o = 16; o; o >>= 1) v += __shfl_xor_sync(0xffffffffu, v, o);
        if (lane == 0) s[0] = v;
    }
    __syncthreads();
    v = s[0];
    __syncthreads();
    return v;
}

__device__ __forceinline__ float block_max(float v) {
    __shared__ float s[32];
    #pragma unroll
    for (int o = 16; o; o >>= 1) v = fmaxf(v, __shfl_xor_sync(0xffffffffu, v, o));
    int lane = threadIdx.x & 31, w = threadIdx.x >> 5;
    if (lane == 0) s[w] = v;
    __syncthreads();
    int nw = blockDim.x >> 5;
    v = (threadIdx.x < (unsigned)nw) ? s[threadIdx.x] : -3.402823466e38f;
    if (w == 0) {
        #pragma unroll
        for (int o = 16; o; o >>= 1) v = fmaxf(v, __shfl_xor_sync(0xffffffffu, v, o));
        if (lane == 0) s[0] = v;
    }
    __syncthreads();
    v = s[0];
    __syncthreads();
    return v;
}

// ---------------- embedding + positional encoding (+hi/lo) ----------------
__global__ void embed_k(const int* __restrict__ tok, const float* __restrict__ emb,
                        float* __restrict__ x, bf16* __restrict__ xh, bf16* __restrict__ xl) {
    long long row = blockIdx.x;
    int s = (int)(row & (SEQ - 1));
    int tk = tok[row];
    int t = threadIdx.x;
    #pragma unroll
    for (int j = 0; j < 4; j++) {
        int i = t * 4 + j;
        float freq = (float)exp(-(double)i * (9.210340371976184 / (double)DMODEL));
        float ang = (float)s * freq;
        float pe = (i & 1) ? cosf(ang) : sinf(ang);
        float v = emb[(long long)tk * DMODEL + i] + pe;
        x[row * DMODEL + i] = v;
        bf16 h, l; split_bf16(v, h, l);
        xh[row * DMODEL + i] = h;
        xl[row * DMODEL + i] = l;
    }
}

// ---------------- weight transpose + bf16 split: W[K][N] -> T[N][K] ----------------
__global__ void wconv_k(const float* __restrict__ W, bf16* __restrict__ Th,
                        bf16* __restrict__ Tl, int N, int K) {
    __shared__ float tile[32][33];
    int n0 = blockIdx.x * 32, k0 = blockIdx.y * 32;
    int tx = threadIdx.x, ty = threadIdx.y;          // 32 x 8
    #pragma unroll
    for (int i = 0; i < 4; i++)
        tile[ty + 8 * i][tx] = W[(long long)(k0 + ty + 8 * i) * N + n0 + tx];
    __syncthreads();
    #pragma unroll
    for (int i = 0; i < 4; i++) {
        float v = tile[tx][ty + 8 * i];
        bf16 h, l; split_bf16(v, h, l);
        long long o = (long long)(n0 + ty + 8 * i) * K + k0 + tx;
        Th[o] = h; Tl[o] = l;
    }
}

// ---------------- tensor-core GEMM (bf16 hi/lo triple, fp32 acc) ----------------
// C[m][n] = scale * sum_k A[m][k]*B[n][k]  (+bias[n]) (relu?)  -- B given as [N][K]
// OUT: 0 = fp32 C, 1 = bf16 hi/lo C, 2 = transposed bf16 hi/lo C (C[n][m], ldc = T stride)
#define MMA_BF16(c, a0,a1,a2,a3, b0,b1)                                          \
    asm volatile("mma.sync.aligned.m16n8k16.row.col.f32.bf16.bf16.f32 "          \
                 "{%0,%1,%2,%3}, {%4,%5,%6,%7}, {%8,%9}, {%0,%1,%2,%3};"         \
                 : "+f"(c[0]), "+f"(c[1]), "+f"(c[2]), "+f"(c[3])                \
                 : "r"(a0), "r"(a1), "r"(a2), "r"(a3), "r"(b0), "r"(b1))

template<int OUT, bool RELU>
__global__ __launch_bounds__(128) void gemm_k(
    const bf16* __restrict__ Ah, const bf16* __restrict__ Al,
    long long lda, long long sAb, long long sAh,
    const bf16* __restrict__ Bh, const bf16* __restrict__ Bl,
    long long ldb, long long sBb, long long sBh,
    float* __restrict__ Cf, bf16* __restrict__ Ch, bf16* __restrict__ Cl,
    long long ldc, long long sCb, long long sCh,
    const float* __restrict__ bias, float scale, int K, int nh)
{
    // row stride = 20 words (32 bf16 data + 8 bf16 pad) -> conflict-free frag loads
    __shared__ uint32_t Ash[128 * 20], Asl[128 * 20];
    __shared__ uint32_t Bsh[64 * 20],  Bsl[64 * 20];

    int z = blockIdx.z;
    int zb = z / nh, zh = z - zb * nh;
    Ah += zb * sAb + zh * sAh;  Al += zb * sAb + zh * sAh;
    Bh += zb * sBb + zh * sBh;  Bl += zb * sBb + zh * sBh;

    const int m0 = blockIdx.y * 128;
    const int n0 = blockIdx.x * 64;
    const int t = threadIdx.x;
    const int lane = t & 31, w = t >> 5;
    const int wm = w >> 1, wn = w & 1;

    unsigned aBh = (unsigned)__cvta_generic_to_shared(Ash);
    unsigned aBl = (unsigned)__cvta_generic_to_shared(Asl);
    unsigned bBh = (unsigned)__cvta_generic_to_shared(Bsh);
    unsigned bBl = (unsigned)__cvta_generic_to_shared(Bsl);

    float acc[4][4][4];
    #pragma unroll
    for (int i = 0; i < 4; i++)
        #pragma unroll
        for (int j = 0; j < 4; j++)
            #pragma unroll
            for (int r = 0; r < 4; r++) acc[i][j][r] = 0.f;

    for (int k0 = 0; k0 < K; k0 += 32) {
        // ---- load tile (cp.async, 16B chunks) ----
        #pragma unroll
        for (int i = 0; i < 4; i++) {               // A: 128 rows x 64B
            int id = i * 128 + t;
            int row = id >> 2, cb = id & 3;
            long long go = (long long)(m0 + row) * lda + k0 + cb * 8;
            unsigned so = row * 80 + cb * 16;
            cpasync16(aBh + so, Ah + go);
            cpasync16(aBl + so, Al + go);
        }
        #pragma unroll
        for (int i = 0; i < 2; i++) {               // B: 64 rows x 64B
            int id = i * 128 + t;
            int row = id >> 2, cb = id & 3;
            long long go = (long long)(n0 + row) * ldb + k0 + cb * 8;
            unsigned so = row * 80 + cb * 16;
            cpasync16(bBh + so, Bh + go);
            cpasync16(bBl + so, Bl + go);
        }
        asm volatile("cp.async.commit_group;");
        asm volatile("cp.async.wait_group 0;" ::: "memory");
        __syncthreads();

        // ---- compute: 2 x k16 steps ----
        #pragma unroll
        for (int s = 0; s < 2; s++) {
            const int kw = s * 8;
            uint32_t bh[4][2], bl[4][2];
            #pragma unroll
            for (int j = 0; j < 4; j++) {
                int idx = (wn * 32 + j * 8 + (lane >> 2)) * 20 + kw + (lane & 3);
                bh[j][0] = Bsh[idx]; bh[j][1] = Bsh[idx + 4];
                bl[j][0] = Bsl[idx]; bl[j][1] = Bsl[idx + 4];
            }
            #pragma unroll
            for (int i = 0; i < 4; i++) {
                int idx = (wm * 64 + i * 16 + (lane >> 2)) * 20 + kw + (lane & 3);
                uint32_t ah0 = Ash[idx],       ah1 = Ash[idx + 160];
                uint32_t ah2 = Ash[idx + 4],   ah3 = Ash[idx + 164];
                uint32_t al0 = Asl[idx],       al1 = Asl[idx + 160];
                uint32_t al2 = Asl[idx + 4],   al3 = Asl[idx + 164];
                #pragma unroll
                for (int j = 0; j < 4; j++) {
                    MMA_BF16(acc[i][j], ah0, ah1, ah2, ah3, bh[j][0], bh[j][1]);
                    MMA_BF16(acc[i][j], ah0, ah1, ah2, ah3, bl[j][0], bl[j][1]);
                    MMA_BF16(acc[i][j], al0, al1, al2, al3, bh[j][0], bh[j][1]);
                }
            }
        }
        __syncthreads();
    }

    // ---- epilogue ----
    float* CfB = Cf ? Cf + zb * sCb + zh * sCh : nullptr;
    bf16*  ChB = Ch ? Ch + zb * sCb + zh * sCh : nullptr;
    bf16*  ClB = Cl ? Cl + zb * sCb + zh * sCh : nullptr;

    #pragma unroll
    for (int i = 0; i < 4; i++) {
        int r0 = m0 + wm * 64 + i * 16 + (lane >> 2);
        int r1 = r0 + 8;
        #pragma unroll
        for (int j = 0; j < 4; j++) {
            int n = n0 + wn * 32 + j * 8 + 2 * (lane & 3);
            float b0v = 0.f, b1v = 0.f;
            if (bias) { b0v = bias[n]; b1v = bias[n + 1]; }
            float v00 = acc[i][j][0] * scale + b0v;
            float v01 = acc[i][j][1] * scale + b1v;
            float v10 = acc[i][j][2] * scale + b0v;
            float v11 = acc[i][j][3] * scale + b1v;
            if (RELU) {
                v00 = fmaxf(v00, 0.f); v01 = fmaxf(v01, 0.f);
                v10 = fmaxf(v10, 0.f); v11 = fmaxf(v11, 0.f);
            }
            if (OUT == 0) {
                *(float2*)(CfB + (long long)r0 * ldc + n) = make_float2(v00, v01);
                *(float2*)(CfB + (long long)r1 * ldc + n) = make_float2(v10, v11);
            } else if (OUT == 1) {
                __nv_bfloat162 h, l;
                split_bf16(v00, h.x, l.x); split_bf16(v01, h.y, l.y);
                *(__nv_bfloat162*)(ChB + (long long)r0 * ldc + n) = h;
                *(__nv_bfloat162*)(ClB + (long long)r0 * ldc + n) = l;
                split_bf16(v10, h.x, l.x); split_bf16(v11, h.y, l.y);
                *(__nv_bfloat162*)(ChB + (long long)r1 * ldc + n) = h;
                *(__nv_bfloat162*)(ClB + (long long)r1 * ldc + n) = l;
            } else {
                bf16 h, l;
                split_bf16(v00, h, l); ChB[(long long)n * ldc + r0] = h; ClB[(long long)n * ldc + r0] = l;
                split_bf16(v01, h, l); ChB[(long long)(n + 1) * ldc + r0] = h; ClB[(long long)(n + 1) * ldc + r0] = l;
                split_bf16(v10, h, l); ChB[(long long)n * ldc + r1] = h; ClB[(long long)n * ldc + r1] = l;
                split_bf16(v11, h, l); ChB[(long long)(n + 1) * ldc + r1] = h; ClB[(long long)(n + 1) * ldc + r1] = l;
            }
        }
    }
}

// ---------------- softmax over rows of 1024, emits bf16 hi/lo probs ----------------
__global__ void softmax_k(const float* __restrict__ sc,
                          bf16* __restrict__ ph, bf16* __restrict__ pl) {
    long long row = blockIdx.x;
    const float* p = sc + row * SEQ;
    int t = threadIdx.x;
    float4 v = *(const float4*)(p + t * 4);
    float mx = block_max(fmaxf(fmaxf(v.x, v.y), fmaxf(v.z, v.w)));
    v.x = expf(v.x - mx); v.y = expf(v.y - mx);
    v.z = expf(v.z - mx); v.w = expf(v.w - mx);
    float s = block_sum(v.x + v.y + v.z + v.w);
    float inv = 1.f / s;
    v.x *= inv; v.y *= inv; v.z *= inv; v.w *= inv;
    __nv_bfloat162 h0, l0, h1, l1;
    split_bf16(v.x, h0.x, l0.x); split_bf16(v.y, h0.y, l0.y);
    split_bf16(v.z, h1.x, l1.x); split_bf16(v.w, h1.y, l1.y);
    long long o = row * SEQ + t * 4;
    *(__nv_bfloat162*)(ph + o) = h0; *(__nv_bfloat162*)(ph + o + 2) = h1;
    *(__nv_bfloat162*)(pl + o) = l0; *(__nv_bfloat162*)(pl + o + 2) = l1;
}

// ---------------- fused residual add + LayerNorm (optionally emits hi/lo) ----------
template<bool WH>
__global__ void addln_k(const float* __restrict__ a, const float* __restrict__ b,
                        const float* __restrict__ g, const float* __restrict__ be,
                        float* __restrict__ o, bf16* __restrict__ oh, bf16* __restrict__ ol) {
    long long row = blockIdx.x;
    int t = threadIdx.x;
    float4 av = *(const float4*)(a + row * DMODEL + t * 4);
    float4 bv = *(const float4*)(b + row * DMODEL + t * 4);
    float x0 = av.x + bv.x, x1 = av.y + bv.y, x2 = av.z + bv.z, x3 = av.w + bv.w;
    float m = block_sum(x0 + x1 + x2 + x3) * (1.f / DMODEL);
    float d0 = x0 - m, d1 = x1 - m, d2 = x2 - m, d3 = x3 - m;
    float var = block_sum(d0 * d0 + d1 * d1 + d2 * d2 + d3 * d3) * (1.f / DMODEL);
    float r = rsqrtf(var + LN_EPS);
    float4 gv = *(const float4*)(g + t * 4);
    float4 ev = *(const float4*)(be + t * 4);
    float4 ov;
    ov.x = d0 * r * gv.x + ev.x;
    ov.y = d1 * r * gv.y + ev.y;
    ov.z = d2 * r * gv.z + ev.z;
    ov.w = d3 * r * gv.w + ev.w;
    *(float4*)(o + row * DMODEL + t * 4) = ov;
    if (WH) {
        __nv_bfloat162 h0, l0, h1, l1;
        split_bf16(ov.x, h0.x, l0.x); split_bf16(ov.y, h0.y, l0.y);
        split_bf16(ov.z, h1.x, l1.x); split_bf16(ov.w, h1.y, l1.y);
        long long off = row * DMODEL + t * 4;
        *(__nv_bfloat162*)(oh + off) = h0; *(__nv_bfloat162*)(oh + off + 2) = h1;
        *(__nv_bfloat162*)(ol + off) = l0; *(__nv_bfloat162*)(ol + off + 2) = l1;
    }
}

// ---------------- launch ----------------
extern "C" void kernel_launch(void* const* d_in, const int* in_sizes, int n_in,
                              void* d_out, int out_size)
{
    const int*   tok = (const int*)d_in[0];
    const float* emb = (const float*)d_in[1];
    const float* Wq = (const float*)d_in[2],  *bq = (const float*)d_in[3];
    const float* Wk = (const float*)d_in[4],  *bk = (const float*)d_in[5];
    const float* Wv = (const float*)d_in[6],  *bv = (const float*)d_in[7];
    const float* Wo = (const float*)d_in[8],  *bo = (const float*)d_in[9];
    const float* W1 = (const float*)d_in[10], *b1 = (const float*)d_in[11];
    const float* W2 = (const float*)d_in[12], *b2 = (const float*)d_in[13];
    const float* lg = (const float*)d_in[14], *lb = (const float*)d_in[15];
    float* out = (float*)d_out;

    float *x, *y, *sc;
    bf16 *xh, *xl, *qh, *ql, *kh, *kl, *vTh, *vTl, *ah, *al, *h1h, *h1l, *ph, *pl;
    bf16 *wqTh, *wqTl, *wkTh, *wkTl, *wvTh, *wvTl, *woTh, *woTl, *w1Th, *w1Tl, *w2Th, *w2Tl;
    cudaGetSymbolAddress((void**)&x,   g_x);
    cudaGetSymbolAddress((void**)&y,   g_y);
    cudaGetSymbolAddress((void**)&sc,  g_sc);
    cudaGetSymbolAddress((void**)&xh,  g_xh);   cudaGetSymbolAddress((void**)&xl,  g_xl);
    cudaGetSymbolAddress((void**)&qh,  g_qh);   cudaGetSymbolAddress((void**)&ql,  g_ql);
    cudaGetSymbolAddress((void**)&kh,  g_kh);   cudaGetSymbolAddress((void**)&kl,  g_kl);
    cudaGetSymbolAddress((void**)&vTh, g_vTh);  cudaGetSymbolAddress((void**)&vTl, g_vTl);
    cudaGetSymbolAddress((void**)&ah,  g_ah);   cudaGetSymbolAddress((void**)&al,  g_al);
    cudaGetSymbolAddress((void**)&h1h, g_h1h);  cudaGetSymbolAddress((void**)&h1l, g_h1l);
    cudaGetSymbolAddress((void**)&ph,  g_ph);   cudaGetSymbolAddress((void**)&pl,  g_pl);
    cudaGetSymbolAddress((void**)&wqTh, g_wqTh); cudaGetSymbolAddress((void**)&wqTl, g_wqTl);
    cudaGetSymbolAddress((void**)&wkTh, g_wkTh); cudaGetSymbolAddress((void**)&wkTl, g_wkTl);
    cudaGetSymbolAddress((void**)&wvTh, g_wvTh); cudaGetSymbolAddress((void**)&wvTl, g_wvTl);
    cudaGetSymbolAddress((void**)&woTh, g_woTh); cudaGetSymbolAddress((void**)&woTl, g_woTl);
    cudaGetSymbolAddress((void**)&w1Th, g_w1Th); cudaGetSymbolAddress((void**)&w1Tl, g_w1Tl);
    cudaGetSymbolAddress((void**)&w2Th, g_w2Th); cudaGetSymbolAddress((void**)&w2Tl, g_w2Tl);

    // ---- convert + transpose all weights (all layers) ----
    dim3 cb(32, 8);
    for (int i = 0; i < NLAYERS; i++) {
        long long woff = (long long)i * DMODEL * DMODEL;
        long long foff = (long long)i * DMODEL * DFF;
        wconv_k<<<dim3(16, 16), cb>>>(Wq + woff, wqTh + woff, wqTl + woff, DMODEL, DMODEL);
        wconv_k<<<dim3(16, 16), cb>>>(Wk + woff, wkTh + woff, wkTl + woff, DMODEL, DMODEL);
        wconv_k<<<dim3(16, 16), cb>>>(Wv + woff, wvTh + woff, wvTl + woff, DMODEL, DMODEL);
        wconv_k<<<dim3(16, 16), cb>>>(Wo + woff, woTh + woff, woTl + woff, DMODEL, DMODEL);
        wconv_k<<<dim3(64, 16), cb>>>(W1 + foff, w1Th + foff, w1Tl + foff, DFF, DMODEL);
        wconv_k<<<dim3(16, 64), cb>>>(W2 + foff, w2Th + foff, w2Tl + foff, DMODEL, DFF);
    }

    embed_k<<<TOKENS, 128>>>(tok, emb, x, xh, xl);

    const long long SDB = (long long)SEQ * DMODEL;       // 524288
    const long long SCB = (long long)NHEADS * SEQ * SEQ; // 8388608
    const long long SCH = (long long)SEQ * SEQ;          // 1048576

    for (int i = 0; i < NLAYERS; i++) {
        long long woff = (long long)i * DMODEL * DMODEL;
        long long foff = (long long)i * DMODEL * DFF;
        const float* bqi = bq + (long long)i * DMODEL;
        const float* bki = bk + (long long)i * DMODEL;
        const float* bvi = bv + (long long)i * DMODEL;
        const float* boi = bo + (long long)i * DMODEL;
        const float* b1i = b1 + (long long)i * DFF;
        const float* b2i = b2 + (long long)i * DMODEL;
        const float* lgi = lg + (long long)i * DMODEL;
        const float* lbi = lb + (long long)i * DMODEL;

        // Q, K projections -> bf16 hi/lo [4096][512]
        gemm_k<1, false><<<dim3(8, 32, 1), 128>>>(
            xh, xl, DMODEL, 0, 0, wqTh + woff, wqTl + woff, DMODEL, 0, 0,
            nullptr, qh, ql, DMODEL, 0, 0, bqi, 1.f, DMODEL, 1);
        gemm_k<1, false><<<dim3(8, 32, 1), 128>>>(
            xh, xl, DMODEL, 0, 0, wkTh + woff, wkTl + woff, DMODEL, 0, 0,
            nullptr, kh, kl, DMODEL, 0, 0, bki, 1.f, DMODEL, 1);
        // V projection -> transposed bf16 hi/lo [512][4096]
        gemm_k<2, false><<<dim3(8, 32, 1), 128>>>(
            xh, xl, DMODEL, 0, 0, wvTh + woff, wvTl + woff, DMODEL, 0, 0,
            nullptr, vTh, vTl, TOKENS, 0, 0, bvi, 1.f, DMODEL, 1);

        // scores = (q @ k^T)/8 per (b,h): M=N=1024, K=64 -> fp32
        gemm_k<0, false><<<dim3(16, 8, BATCH * NHEADS), 128>>>(
            qh, ql, DMODEL, SDB, DHEAD, kh, kl, DMODEL, SDB, DHEAD,
            sc, nullptr, nullptr, SEQ, SCB, SCH, nullptr, 0.125f, DHEAD, NHEADS);

        softmax_k<<<BATCH * NHEADS * SEQ, 256>>>(sc, ph, pl);

        // attn = probs @ v : M=1024, N=64, K=1024 -> bf16 hi/lo in bugged layout
        gemm_k<1, false><<<dim3(1, 8, BATCH * NHEADS), 128>>>(
            ph, pl, SEQ, SCB, SCH, vTh, vTl, TOKENS, SEQ, (long long)DHEAD * TOKENS,
            nullptr, ah, al, DHEAD, SDB, (long long)SEQ * DHEAD, nullptr, 1.f, SEQ, NHEADS);

        // O projection (bugged-layout attn viewed [4096][512]) -> fp32 y
        gemm_k<0, false><<<dim3(8, 32, 1), 128>>>(
            ah, al, DMODEL, 0, 0, woTh + woff, woTl + woff, DMODEL, 0, 0,
            y, nullptr, nullptr, DMODEL, 0, 0, boi, 1.f, DMODEL, 1);

        addln_k<true><<<TOKENS, 128>>>(x, y, lgi, lbi, x, xh, xl);

        // FFN1 (relu) -> bf16 hi/lo [4096][2048]
        gemm_k<1, true><<<dim3(32, 32, 1), 128>>>(
            xh, xl, DMODEL, 0, 0, w1Th + foff, w1Tl + foff, DMODEL, 0, 0,
            nullptr, h1h, h1l, DFF, 0, 0, b1i, 1.f, DMODEL, 1);
        // FFN2 -> fp32 y
        gemm_k<0, false><<<dim3(8, 32, 1), 128>>>(
            h1h, h1l, DFF, 0, 0, w2Th + foff, w2Tl + foff, DFF, 0, 0,
            y, nullptr, nullptr, DMODEL, 0, 0, b2i, 1.f, DFF, 1);

        if (i == NLAYERS - 1)
            addln_k<false><<<TOKENS, 128>>>(x, y, lgi, lbi, out, nullptr, nullptr);
        else
            addln_k<true><<<TOKENS, 128>>>(x, y, lgi, lbi, x, xh, xl);
    }
}

// round 4
// speedup vs baseline: 3.5339x; 1.0591x over previous
#include <cuda_runtime.h>
#include <cuda_bf16.h>
#include <math.h>
#include <cstdint>

#define NLAYERS 6
#define DMODEL  512
#define NHEADS  8
#define DHEAD   64
#define BATCH   4
#define SEQ     1024
#define TOKENS  (BATCH*SEQ)      // 4096
#define DFF     2048
#define LN_EPS  1e-5f

typedef __nv_bfloat16 bf16;

// ---------------- scratch (device globals; no allocation allowed) ----------------
__device__ __align__(16) float g_x  [TOKENS*DMODEL];
__device__ __align__(16) float g_y  [TOKENS*DMODEL];
__device__ __align__(16) float g_sc [(size_t)BATCH*NHEADS*SEQ*SEQ]; // 134 MB fp32 scores

__device__ __align__(16) bf16 g_xh[TOKENS*DMODEL],  g_xl[TOKENS*DMODEL];
__device__ __align__(16) bf16 g_qh[TOKENS*DMODEL],  g_ql[TOKENS*DMODEL];
__device__ __align__(16) bf16 g_kh[TOKENS*DMODEL],  g_kl[TOKENS*DMODEL];
__device__ __align__(16) bf16 g_vTh[TOKENS*DMODEL], g_vTl[TOKENS*DMODEL];   // [512][4096]
__device__ __align__(16) bf16 g_ah[TOKENS*DMODEL],  g_al[TOKENS*DMODEL];
__device__ __align__(16) bf16 g_h1h[TOKENS*DFF],    g_h1l[TOKENS*DFF];
__device__ __align__(16) bf16 g_ph[(size_t)BATCH*NHEADS*SEQ*SEQ], g_pl[(size_t)BATCH*NHEADS*SEQ*SEQ];

// transposed bf16 weights (all layers)
__device__ __align__(16) bf16 g_wqTh[NLAYERS*DMODEL*DMODEL], g_wqTl[NLAYERS*DMODEL*DMODEL];
__device__ __align__(16) bf16 g_wkTh[NLAYERS*DMODEL*DMODEL], g_wkTl[NLAYERS*DMODEL*DMODEL];
__device__ __align__(16) bf16 g_wvTh[NLAYERS*DMODEL*DMODEL], g_wvTl[NLAYERS*DMODEL*DMODEL];
__device__ __align__(16) bf16 g_woTh[NLAYERS*DMODEL*DMODEL], g_woTl[NLAYERS*DMODEL*DMODEL];
__device__ __align__(16) bf16 g_w1Th[NLAYERS*DMODEL*DFF],    g_w1Tl[NLAYERS*DMODEL*DFF];
__device__ __align__(16) bf16 g_w2Th[NLAYERS*DMODEL*DFF],    g_w2Tl[NLAYERS*DMODEL*DFF];

// ---------------- helpers ----------------
__device__ __forceinline__ void split_bf16(float v, bf16& h, bf16& l) {
    h = __float2bfloat16_rn(v);
    l = __float2bfloat16_rn(v - __bfloat162float(h));
}

__device__ __forceinline__ void cpasync16(unsigned saddr, const void* g) {
    asm volatile("cp.async.cg.shared.global [%0], [%1], 16;\n" :: "r"(saddr), "l"(g));
}

__device__ __forceinline__ float block_sum(float v) {
    __shared__ float s[32];
    #pragma unroll
    for (int o = 16; o; o >>= 1) v += __shfl_xor_sync(0xffffffffu, v, o);
    int lane = threadIdx.x & 31, w = threadIdx.x >> 5;
    if (lane == 0) s[w] = v;
    __syncthreads();
    int nw = blockDim.x >> 5;
    v = (threadIdx.x < (unsigned)nw) ? s[threadIdx.x] : 0.f;
    if (w == 0) {
        #pragma unroll
        for (int o = 16; o; o >>= 1) v += __shfl_xor_sync(0xffffffffu, v, o);
        if (lane == 0) s[0] = v;
    }
    __syncthreads();
    v = s[0];
    __syncthreads();
    return v;
}

__device__ __forceinline__ float block_max(float v) {
    __shared__ float s[32];
    #pragma unroll
    for (int o = 16; o; o >>= 1) v = fmaxf(v, __shfl_xor_sync(0xffffffffu, v, o));
    int lane = threadIdx.x & 31, w = threadIdx.x >> 5;
    if (lane == 0) s[w] = v;
    __syncthreads();
    int nw = blockDim.x >> 5;
    v = (threadIdx.x < (unsigned)nw) ? s[threadIdx.x] : -3.402823466e38f;
    if (w == 0) {
        #pragma unroll
        for (int o = 16; o; o >>= 1) v = fmaxf(v, __shfl_xor_sync(0xffffffffu, v, o));
        if (lane == 0) s[0] = v;
    }
    __syncthreads();
    v = s[0];
    __syncthreads();
    return v;
}

// ---------------- embedding + positional encoding (+hi/lo) ----------------
__global__ void embed_k(const int* __restrict__ tok, const float* __restrict__ emb,
                        float* __restrict__ x, bf16* __restrict__ xh, bf16* __restrict__ xl) {
    long long row = blockIdx.x;
    int s = (int)(row & (SEQ - 1));
    int tk = tok[row];
    int t = threadIdx.x;
    #pragma unroll
    for (int j = 0; j < 4; j++) {
        int i = t * 4 + j;
        float freq = (float)exp(-(double)i * (9.210340371976184 / (double)DMODEL));
        float ang = (float)s * freq;
        float pe = (i & 1) ? cosf(ang) : sinf(ang);
        float v = emb[(long long)tk * DMODEL + i] + pe;
        x[row * DMODEL + i] = v;
        bf16 h, l; split_bf16(v, h, l);
        xh[row * DMODEL + i] = h;
        xl[row * DMODEL + i] = l;
    }
}

// ------- weight transpose + bf16 split: W[K][N] -> T[N][K], batched over layers -------
__global__ void wconv_k(const float* __restrict__ W, bf16* __restrict__ Th,
                        bf16* __restrict__ Tl, int N, int K) {
    __shared__ float tile[32][33];
    long long loff = (long long)blockIdx.z * N * K;
    W += loff; Th += loff; Tl += loff;
    int n0 = blockIdx.x * 32, k0 = blockIdx.y * 32;
    int tx = threadIdx.x, ty = threadIdx.y;          // 32 x 8
    #pragma unroll
    for (int i = 0; i < 4; i++)
        tile[ty + 8 * i][tx] = W[(long long)(k0 + ty + 8 * i) * N + n0 + tx];
    __syncthreads();
    #pragma unroll
    for (int i = 0; i < 4; i++) {
        float v = tile[tx][ty + 8 * i];
        bf16 h, l; split_bf16(v, h, l);
        long long o = (long long)(n0 + ty + 8 * i) * K + k0 + tx;
        Th[o] = h; Tl[o] = l;
    }
}

// ---------------- tensor-core GEMM (bf16 hi/lo triple, fp32 acc) ----------------
// Double-buffered cp.async pipeline, 256 threads, warp grid 2(M)x4(N).
// C[m][n] = scale * sum_k A[m][k]*B[n][k]  (+bias[n]) (relu?)  -- B given as [N][K]
// OUT: 0 = fp32 C, 1 = bf16 hi/lo C, 2 = transposed bf16 hi/lo C (C[n][m])
#define MMA_BF16(c, a0,a1,a2,a3, b0,b1)                                          \
    asm volatile("mma.sync.aligned.m16n8k16.row.col.f32.bf16.bf16.f32 "          \
                 "{%0,%1,%2,%3}, {%4,%5,%6,%7}, {%8,%9}, {%0,%1,%2,%3};"         \
                 : "+f"(c[0]), "+f"(c[1]), "+f"(c[2]), "+f"(c[3])                \
                 : "r"(a0), "r"(a1), "r"(a2), "r"(a3), "r"(b0), "r"(b1))

template<int BM, int BN, int OUT, bool RELU>
__global__ __launch_bounds__(256) void gemm_k(
    const bf16* __restrict__ Ah, const bf16* __restrict__ Al,
    long long lda, long long sAb, long long sAh,
    const bf16* __restrict__ Bh, const bf16* __restrict__ Bl,
    long long ldb, long long sBb, long long sBh,
    float* __restrict__ Cf, bf16* __restrict__ Ch, bf16* __restrict__ Cl,
    long long ldc, long long sCb, long long sCh,
    const float* __restrict__ bias, float scale, int K, int nh)
{
    // word layout per stage: Ah[BM*20] Al[BM*20] Bh[BN*20] Bl[BN*20]  (20-word padded rows)
    extern __shared__ uint32_t sm[];
    const int AW = BM * 20, BW = BN * 20;
    const int SS = 2 * AW + 2 * BW;                    // words per stage

    int z = blockIdx.z;
    int zb = z / nh, zh = z - zb * nh;
    Ah += zb * sAb + zh * sAh;  Al += zb * sAb + zh * sAh;
    Bh += zb * sBb + zh * sBh;  Bl += zb * sBb + zh * sBh;

    const int m0 = blockIdx.y * BM;
    const int n0 = blockIdx.x * BN;
    const int t = threadIdx.x;
    const int lane = t & 31, w = t >> 5;
    const int wm = w >> 2, wn = w & 3;                 // 2 x 4 warp grid
    const int WNW = BN / 4;                            // warp n-width: 32 or 16
    const int NJ  = WNW / 8;                           // n-tiles per warp: 4 or 2

    const unsigned sb = (unsigned)__cvta_generic_to_shared(sm);

    float acc[4][BN / 32][4];
    #pragma unroll
    for (int i = 0; i < 4; i++)
        #pragma unroll
        for (int j = 0; j < BN / 32; j++)
            #pragma unroll
            for (int r = 0; r < 4; r++) acc[i][j][r] = 0.f;

    const int nk = K / 32;

    // ---- stage loader ----
    auto load_stage = [&](int ks, int st) {
        const unsigned base = sb + st * SS * 4;
        const int k0 = ks * 32;
        #pragma unroll
        for (int i = 0; i < (BM * 4) / 256; i++) {     // A: BM rows x 64B (hi & lo)
            int id = i * 256 + t;
            int row = id >> 2, cb = id & 3;
            long long go = (long long)(m0 + row) * lda + k0 + cb * 8;
            unsigned so = row * 80 + cb * 16;
            cpasync16(base + so, Ah + go);
            cpasync16(base + AW * 4 + so, Al + go);
        }
        #pragma unroll
        for (int i = 0; i < (BN * 4) / 256; i++) {     // B: BN rows x 64B (hi & lo)
            int id = i * 256 + t;
            int row = id >> 2, cb = id & 3;
            long long go = (long long)(n0 + row) * ldb + k0 + cb * 8;
            unsigned so = row * 80 + cb * 16;
            cpasync16(base + 2 * AW * 4 + so, Bh + go);
            cpasync16(base + (2 * AW + BW) * 4 + so, Bl + go);
        }
        asm volatile("cp.async.commit_group;");
    };

    load_stage(0, 0);

    for (int ks = 0; ks < nk; ks++) {
        if (ks + 1 < nk) {
            load_stage(ks + 1, (ks + 1) & 1);
            asm volatile("cp.async.wait_group 1;" ::: "memory");
        } else {
            asm volatile("cp.async.wait_group 0;" ::: "memory");
        }
        __syncthreads();

        const uint32_t* Ash = sm + (ks & 1) * SS;
        const uint32_t* Asl = Ash + AW;
        const uint32_t* Bsh = Ash + 2 * AW;
        const uint32_t* Bsl = Ash + 2 * AW + BW;

        #pragma unroll
        for (int s = 0; s < 2; s++) {
            const int kw = s * 8;
            uint32_t bh[BN / 32][2], bl[BN / 32][2];
            #pragma unroll
            for (int j = 0; j < NJ; j++) {
                int idx = (wn * WNW + j * 8 + (lane >> 2)) * 20 + kw + (lane & 3);
                bh[j][0] = Bsh[idx]; bh[j][1] = Bsh[idx + 4];
                bl[j][0] = Bsl[idx]; bl[j][1] = Bsl[idx + 4];
            }
            #pragma unroll
            for (int i = 0; i < 4; i++) {
                int idx = (wm * 64 + i * 16 + (lane >> 2)) * 20 + kw + (lane & 3);
                uint32_t ah0 = Ash[idx],       ah1 = Ash[idx + 160];
                uint32_t ah2 = Ash[idx + 4],   ah3 = Ash[idx + 164];
                uint32_t al0 = Asl[idx],       al1 = Asl[idx + 160];
                uint32_t al2 = Asl[idx + 4],   al3 = Asl[idx + 164];
                #pragma unroll
                for (int j = 0; j < NJ; j++) {
                    MMA_BF16(acc[i][j], ah0, ah1, ah2, ah3, bh[j][0], bh[j][1]);
                    MMA_BF16(acc[i][j], ah0, ah1, ah2, ah3, bl[j][0], bl[j][1]);
                    MMA_BF16(acc[i][j], al0, al1, al2, al3, bh[j][0], bh[j][1]);
                }
            }
        }
        __syncthreads();
    }

    // ---- epilogue ----
    float* CfB = Cf ? Cf + zb * sCb + zh * sCh : nullptr;
    bf16*  ChB = Ch ? Ch + zb * sCb + zh * sCh : nullptr;
    bf16*  ClB = Cl ? Cl + zb * sCb + zh * sCh : nullptr;

    #pragma unroll
    for (int i = 0; i < 4; i++) {
        int r0 = m0 + wm * 64 + i * 16 + (lane >> 2);
        int r1 = r0 + 8;
        #pragma unroll
        for (int j = 0; j < NJ; j++) {
            int n = n0 + wn * WNW + j * 8 + 2 * (lane & 3);
            float b0v = 0.f, b1v = 0.f;
            if (bias) { b0v = bias[n]; b1v = bias[n + 1]; }
            float v00 = acc[i][j][0] * scale + b0v;
            float v01 = acc[i][j][1] * scale + b1v;
            float v10 = acc[i][j][2] * scale + b0v;
            float v11 = acc[i][j][3] * scale + b1v;
            if (RELU) {
                v00 = fmaxf(v00, 0.f); v01 = fmaxf(v01, 0.f);
                v10 = fmaxf(v10, 0.f); v11 = fmaxf(v11, 0.f);
            }
            if (OUT == 0) {
                *(float2*)(CfB + (long long)r0 * ldc + n) = make_float2(v00, v01);
                *(float2*)(CfB + (long long)r1 * ldc + n) = make_float2(v10, v11);
            } else if (OUT == 1) {
                __nv_bfloat162 h, l;
                split_bf16(v00, h.x, l.x); split_bf16(v01, h.y, l.y);
                *(__nv_bfloat162*)(ChB + (long long)r0 * ldc + n) = h;
                *(__nv_bfloat162*)(ClB + (long long)r0 * ldc + n) = l;
                split_bf16(v10, h.x, l.x); split_bf16(v11, h.y, l.y);
                *(__nv_bfloat162*)(ChB + (long long)r1 * ldc + n) = h;
                *(__nv_bfloat162*)(ClB + (long long)r1 * ldc + n) = l;
            } else {
                bf16 h, l;
                split_bf16(v00, h, l); ChB[(long long)n * ldc + r0] = h; ClB[(long long)n * ldc + r0] = l;
                split_bf16(v01, h, l); ChB[(long long)(n + 1) * ldc + r0] = h; ClB[(long long)(n + 1) * ldc + r0] = l;
                split_bf16(v10, h, l); ChB[(long long)n * ldc + r1] = h; ClB[(long long)n * ldc + r1] = l;
                split_bf16(v11, h, l); ChB[(long long)(n + 1) * ldc + r1] = h; ClB[(long long)(n + 1) * ldc + r1] = l;
            }
        }
    }
}

// smem bytes for a tile config
#define GSMEM(BM, BN) ((2 * ((BM) * 20) + 2 * ((BN) * 20)) * 2 * 4)

// ---------------- softmax over rows of 1024, emits bf16 hi/lo probs ----------------
__global__ void softmax_k(const float* __restrict__ sc,
                          bf16* __restrict__ ph, bf16* __restrict__ pl) {
    long long row = blockIdx.x;
    const float* p = sc + row * SEQ;
    int t = threadIdx.x;
    float4 v = *(const float4*)(p + t * 4);
    float mx = block_max(fmaxf(fmaxf(v.x, v.y), fmaxf(v.z, v.w)));
    v.x = expf(v.x - mx); v.y = expf(v.y - mx);
    v.z = expf(v.z - mx); v.w = expf(v.w - mx);
    float s = block_sum(v.x + v.y + v.z + v.w);
    float inv = 1.f / s;
    v.x *= inv; v.y *= inv; v.z *= inv; v.w *= inv;
    __nv_bfloat162 h0, l0, h1, l1;
    split_bf16(v.x, h0.x, l0.x); split_bf16(v.y, h0.y, l0.y);
    split_bf16(v.z, h1.x, l1.x); split_bf16(v.w, h1.y, l1.y);
    long long o = row * SEQ + t * 4;
    *(__nv_bfloat162*)(ph + o) = h0; *(__nv_bfloat162*)(ph + o + 2) = h1;
    *(__nv_bfloat162*)(pl + o) = l0; *(__nv_bfloat162*)(pl + o + 2) = l1;
}

// ---------------- fused residual add + LayerNorm (optionally emits hi/lo) ----------
template<bool WH>
__global__ void addln_k(const float* __restrict__ a, const float* __restrict__ b,
                        const float* __restrict__ g, const float* __restrict__ be,
                        float* __restrict__ o, bf16* __restrict__ oh, bf16* __restrict__ ol) {
    long long row = blockIdx.x;
    int t = threadIdx.x;
    float4 av = *(const float4*)(a + row * DMODEL + t * 4);
    float4 bv = *(const float4*)(b + row * DMODEL + t * 4);
    float x0 = av.x + bv.x, x1 = av.y + bv.y, x2 = av.z + bv.z, x3 = av.w + bv.w;
    float m = block_sum(x0 + x1 + x2 + x3) * (1.f / DMODEL);
    float d0 = x0 - m, d1 = x1 - m, d2 = x2 - m, d3 = x3 - m;
    float var = block_sum(d0 * d0 + d1 * d1 + d2 * d2 + d3 * d3) * (1.f / DMODEL);
    float r = rsqrtf(var + LN_EPS);
    float4 gv = *(const float4*)(g + t * 4);
    float4 ev = *(const float4*)(be + t * 4);
    float4 ov;
    ov.x = d0 * r * gv.x + ev.x;
    ov.y = d1 * r * gv.y + ev.y;
    ov.z = d2 * r * gv.z + ev.z;
    ov.w = d3 * r * gv.w + ev.w;
    *(float4*)(o + row * DMODEL + t * 4) = ov;
    if (WH) {
        __nv_bfloat162 h0, l0, h1, l1;
        split_bf16(ov.x, h0.x, l0.x); split_bf16(ov.y, h0.y, l0.y);
        split_bf16(ov.z, h1.x, l1.x); split_bf16(ov.w, h1.y, l1.y);
        long long off = row * DMODEL + t * 4;
        *(__nv_bfloat162*)(oh + off) = h0; *(__nv_bfloat162*)(oh + off + 2) = h1;
        *(__nv_bfloat162*)(ol + off) = l0; *(__nv_bfloat162*)(ol + off + 2) = l1;
    }
}

// ---------------- launch ----------------
extern "C" void kernel_launch(void* const* d_in, const int* in_sizes, int n_in,
                              void* d_out, int out_size)
{
    const int*   tok = (const int*)d_in[0];
    const float* emb = (const float*)d_in[1];
    const float* Wq = (const float*)d_in[2],  *bq = (const float*)d_in[3];
    const float* Wk = (const float*)d_in[4],  *bk = (const float*)d_in[5];
    const float* Wv = (const float*)d_in[6],  *bv = (const float*)d_in[7];
    const float* Wo = (const float*)d_in[8],  *bo = (const float*)d_in[9];
    const float* W1 = (const float*)d_in[10], *b1 = (const float*)d_in[11];
    const float* W2 = (const float*)d_in[12], *b2 = (const float*)d_in[13];
    const float* lg = (const float*)d_in[14], *lb = (const float*)d_in[15];
    float* out = (float*)d_out;

    float *x, *y, *sc;
    bf16 *xh, *xl, *qh, *ql, *kh, *kl, *vTh, *vTl, *ah, *al, *h1h, *h1l, *ph, *pl;
    bf16 *wqTh, *wqTl, *wkTh, *wkTl, *wvTh, *wvTl, *woTh, *woTl, *w1Th, *w1Tl, *w2Th, *w2Tl;
    cudaGetSymbolAddress((void**)&x,   g_x);
    cudaGetSymbolAddress((void**)&y,   g_y);
    cudaGetSymbolAddress((void**)&sc,  g_sc);
    cudaGetSymbolAddress((void**)&xh,  g_xh);   cudaGetSymbolAddress((void**)&xl,  g_xl);
    cudaGetSymbolAddress((void**)&qh,  g_qh);   cudaGetSymbolAddress((void**)&ql,  g_ql);
    cudaGetSymbolAddress((void**)&kh,  g_kh);   cudaGetSymbolAddress((void**)&kl,  g_kl);
    cudaGetSymbolAddress((void**)&vTh, g_vTh);  cudaGetSymbolAddress((void**)&vTl, g_vTl);
    cudaGetSymbolAddress((void**)&ah,  g_ah);   cudaGetSymbolAddress((void**)&al,  g_al);
    cudaGetSymbolAddress((void**)&h1h, g_h1h);  cudaGetSymbolAddress((void**)&h1l, g_h1l);
    cudaGetSymbolAddress((void**)&ph,  g_ph);   cudaGetSymbolAddress((void**)&pl,  g_pl);
    cudaGetSymbolAddress((void**)&wqTh, g_wqTh); cudaGetSymbolAddress((void**)&wqTl, g_wqTl);
    cudaGetSymbolAddress((void**)&wkTh, g_wkTh); cudaGetSymbolAddress((void**)&wkTl, g_wkTl);
    cudaGetSymbolAddress((void**)&wvTh, g_wvTh); cudaGetSymbolAddress((void**)&wvTl, g_wvTl);
    cudaGetSymbolAddress((void**)&woTh, g_woTh); cudaGetSymbolAddress((void**)&woTl, g_woTl);
    cudaGetSymbolAddress((void**)&w1Th, g_w1Th); cudaGetSymbolAddress((void**)&w1Tl, g_w1Tl);
    cudaGetSymbolAddress((void**)&w2Th, g_w2Th); cudaGetSymbolAddress((void**)&w2Tl, g_w2Tl);

    // raise dynamic smem limits (idempotent; ignore errors during capture)
    cudaFuncSetAttribute(gemm_k<128,128,0,false>, cudaFuncAttributeMaxDynamicSharedMemorySize, GSMEM(128,128));
    cudaFuncSetAttribute(gemm_k<128,128,1,false>, cudaFuncAttributeMaxDynamicSharedMemorySize, GSMEM(128,128));
    cudaFuncSetAttribute(gemm_k<128,128,2,false>, cudaFuncAttributeMaxDynamicSharedMemorySize, GSMEM(128,128));
    cudaFuncSetAttribute(gemm_k<128,128,1,true >, cudaFuncAttributeMaxDynamicSharedMemorySize, GSMEM(128,128));
    cudaFuncSetAttribute(gemm_k<128, 64,1,false>, cudaFuncAttributeMaxDynamicSharedMemorySize, GSMEM(128,64));

    // ---- convert + transpose all weights (batched over layers) ----
    dim3 cb(32, 8);
    wconv_k<<<dim3(16, 16, NLAYERS), cb>>>(Wq, wqTh, wqTl, DMODEL, DMODEL);
    wconv_k<<<dim3(16, 16, NLAYERS), cb>>>(Wk, wkTh, wkTl, DMODEL, DMODEL);
    wconv_k<<<dim3(16, 16, NLAYERS), cb>>>(Wv, wvTh, wvTl, DMODEL, DMODEL);
    wconv_k<<<dim3(16, 16, NLAYERS), cb>>>(Wo, woTh, woTl, DMODEL, DMODEL);
    wconv_k<<<dim3(64, 16, NLAYERS), cb>>>(W1, w1Th, w1Tl, DFF, DMODEL);
    wconv_k<<<dim3(16, 64, NLAYERS), cb>>>(W2, w2Th, w2Tl, DMODEL, DFF);

    embed_k<<<TOKENS, 128>>>(tok, emb, x, xh, xl);

    const long long SDB = (long long)SEQ * DMODEL;       // 524288
    const long long SCB = (long long)NHEADS * SEQ * SEQ; // 8388608
    const long long SCH = (long long)SEQ * SEQ;          // 1048576
    const int S128 = GSMEM(128,128), S64 = GSMEM(128,64);

    for (int i = 0; i < NLAYERS; i++) {
        long long woff = (long long)i * DMODEL * DMODEL;
        long long foff = (long long)i * DMODEL * DFF;
        const float* bqi = bq + (long long)i * DMODEL;
        const float* bki = bk + (long long)i * DMODEL;
        const float* bvi = bv + (long long)i * DMODEL;
        const float* boi = bo + (long long)i * DMODEL;
        const float* b1i = b1 + (long long)i * DFF;
        const float* b2i = b2 + (long long)i * DMODEL;
        const float* lgi = lg + (long long)i * DMODEL;
        const float* lbi = lb + (long long)i * DMODEL;

        // Q, K projections -> bf16 hi/lo [4096][512]
        gemm_k<128,128,1,false><<<dim3(4, 32, 1), 256, S128>>>(
            xh, xl, DMODEL, 0, 0, wqTh + woff, wqTl + woff, DMODEL, 0, 0,
            nullptr, qh, ql, DMODEL, 0, 0, bqi, 1.f, DMODEL, 1);
        gemm_k<128,128,1,false><<<dim3(4, 32, 1), 256, S128>>>(
            xh, xl, DMODEL, 0, 0, wkTh + woff, wkTl + woff, DMODEL, 0, 0,
            nullptr, kh, kl, DMODEL, 0, 0, bki, 1.f, DMODEL, 1);
        // V projection -> transposed bf16 hi/lo [512][4096]
        gemm_k<128,128,2,false><<<dim3(4, 32, 1), 256, S128>>>(
            xh, xl, DMODEL, 0, 0, wvTh + woff, wvTl + woff, DMODEL, 0, 0,
            nullptr, vTh, vTl, TOKENS, 0, 0, bvi, 1.f, DMODEL, 1);

        // scores = (q @ k^T)/8 per (b,h): M=N=1024, K=64 -> fp32
        gemm_k<128,128,0,false><<<dim3(8, 8, BATCH * NHEADS), 256, S128>>>(
            qh, ql, DMODEL, SDB, DHEAD, kh, kl, DMODEL, SDB, DHEAD,
            sc, nullptr, nullptr, SEQ, SCB, SCH, nullptr, 0.125f, DHEAD, NHEADS);

        softmax_k<<<BATCH * NHEADS * SEQ, 256>>>(sc, ph, pl);

        // attn = probs @ v : M=1024, N=64, K=1024 -> bf16 hi/lo in bugged layout
        gemm_k<128,64,1,false><<<dim3(1, 8, BATCH * NHEADS), 256, S64>>>(
            ph, pl, SEQ, SCB, SCH, vTh, vTl, TOKENS, SEQ, (long long)DHEAD * TOKENS,
            nullptr, ah, al, DHEAD, SDB, (long long)SEQ * DHEAD, nullptr, 1.f, SEQ, NHEADS);

        // O projection (bugged-layout attn viewed [4096][512]) -> fp32 y
        gemm_k<128,128,0,false><<<dim3(4, 32, 1), 256, S128>>>(
            ah, al, DMODEL, 0, 0, woTh + woff, woTl + woff, DMODEL, 0, 0,
            y, nullptr, nullptr, DMODEL, 0, 0, boi, 1.f, DMODEL, 1);

        addln_k<true><<<TOKENS, 128>>>(x, y, lgi, lbi, x, xh, xl);

        // FFN1 (relu) -> bf16 hi/lo [4096][2048]
        gemm_k<128,128,1,true><<<dim3(16, 32, 1), 256, S128>>>(
            xh, xl, DMODEL, 0, 0, w1Th + foff, w1Tl + foff, DMODEL, 0, 0,
            nullptr, h1h, h1l, DFF, 0, 0, b1i, 1.f, DMODEL, 1);
        // FFN2 -> fp32 y
        gemm_k<128,128,0,false><<<dim3(4, 32, 1), 256, S128>>>(
            h1h, h1l, DFF, 0, 0, w2Th + foff, w2Tl + foff, DFF, 0, 0,
            y, nullptr, nullptr, DMODEL, 0, 0, b2i, 1.f, DFF, 1);

        if (i == NLAYERS - 1)
            addln_k<false><<<TOKENS, 128>>>(x, y, lgi, lbi, out, nullptr, nullptr);
        else
            addln_k<true><<<TOKENS, 128>>>(x, y, lgi, lbi, x, xh, xl);
    }
}

// round 5
// speedup vs baseline: 4.1504x; 1.1744x over previous
#include <cuda_runtime.h>
#include <cuda_bf16.h>
#include <math.h>
#include <cstdint>

#define NLAYERS 6
#define DMODEL  512
#define NHEADS  8
#define DHEAD   64
#define BATCH   4
#define SEQ     1024
#define TOKENS  (BATCH*SEQ)      // 4096
#define DFF     2048
#define LN_EPS  1e-5f

typedef __nv_bfloat16 bf16;

// ---------------- scratch (device globals; no allocation allowed) ----------------
__device__ __align__(16) float g_x  [TOKENS*DMODEL];
__device__ __align__(16) float g_y  [TOKENS*DMODEL];

__device__ __align__(16) bf16 g_xh[TOKENS*DMODEL],  g_xl[TOKENS*DMODEL];
__device__ __align__(16) bf16 g_qh[TOKENS*DMODEL],  g_ql[TOKENS*DMODEL];
__device__ __align__(16) bf16 g_kh[TOKENS*DMODEL],  g_kl[TOKENS*DMODEL];
__device__ __align__(16) bf16 g_vTh[TOKENS*DMODEL], g_vTl[TOKENS*DMODEL];   // [512][4096]
__device__ __align__(16) bf16 g_ah[TOKENS*DMODEL],  g_al[TOKENS*DMODEL];
__device__ __align__(16) bf16 g_h1h[TOKENS*DFF],    g_h1l[TOKENS*DFF];

// transposed bf16 weights (all layers)
__device__ __align__(16) bf16 g_wqTh[NLAYERS*DMODEL*DMODEL], g_wqTl[NLAYERS*DMODEL*DMODEL];
__device__ __align__(16) bf16 g_wkTh[NLAYERS*DMODEL*DMODEL], g_wkTl[NLAYERS*DMODEL*DMODEL];
__device__ __align__(16) bf16 g_wvTh[NLAYERS*DMODEL*DMODEL], g_wvTl[NLAYERS*DMODEL*DMODEL];
__device__ __align__(16) bf16 g_woTh[NLAYERS*DMODEL*DMODEL], g_woTl[NLAYERS*DMODEL*DMODEL];
__device__ __align__(16) bf16 g_w1Th[NLAYERS*DMODEL*DFF],    g_w1Tl[NLAYERS*DMODEL*DFF];
__device__ __align__(16) bf16 g_w2Th[NLAYERS*DMODEL*DFF],    g_w2Tl[NLAYERS*DMODEL*DFF];

// ---------------- helpers ----------------
__device__ __forceinline__ void split_bf16(float v, bf16& h, bf16& l) {
    h = __float2bfloat16_rn(v);
    l = __float2bfloat16_rn(v - __bfloat162float(h));
}

__device__ __forceinline__ void cpasync16(unsigned saddr, const void* g) {
    asm volatile("cp.async.cg.shared.global [%0], [%1], 16;\n" :: "r"(saddr), "l"(g));
}

__device__ __forceinline__ float block_sum(float v) {
    __shared__ float s[32];
    #pragma unroll
    for (int o = 16; o; o >>= 1) v += __shfl_xor_sync(0xffffffffu, v, o);
    int lane = threadIdx.x & 31, w = threadIdx.x >> 5;
    if (lane == 0) s[w] = v;
    __syncthreads();
    int nw = blockDim.x >> 5;
    v = (threadIdx.x < (unsigned)nw) ? s[threadIdx.x] : 0.f;
    if (w == 0) {
        #pragma unroll
        for (int o = 16; o; o >>= 1) v += __shfl_xor_sync(0xffffffffu, v, o);
        if (lane == 0) s[0] = v;
    }
    __syncthreads();
    v = s[0];
    __syncthreads();
    return v;
}

// ---------------- embedding + positional encoding (+hi/lo) ----------------
__global__ void embed_k(const int* __restrict__ tok, const float* __restrict__ emb,
                        float* __restrict__ x, bf16* __restrict__ xh, bf16* __restrict__ xl) {
    long long row = blockIdx.x;
    int s = (int)(row & (SEQ - 1));
    int tk = tok[row];
    int t = threadIdx.x;
    #pragma unroll
    for (int j = 0; j < 4; j++) {
        int i = t * 4 + j;
        float freq = (float)exp(-(double)i * (9.210340371976184 / (double)DMODEL));
        float ang = (float)s * freq;
        float pe = (i & 1) ? cosf(ang) : sinf(ang);
        float v = emb[(long long)tk * DMODEL + i] + pe;
        x[row * DMODEL + i] = v;
        bf16 h, l; split_bf16(v, h, l);
        xh[row * DMODEL + i] = h;
        xl[row * DMODEL + i] = l;
    }
}

// ------- weight transpose + bf16 split: W[K][N] -> T[N][K], batched over layers -------
__global__ void wconv_k(const float* __restrict__ W, bf16* __restrict__ Th,
                        bf16* __restrict__ Tl, int N, int K) {
    __shared__ float tile[32][33];
    long long loff = (long long)blockIdx.z * N * K;
    W += loff; Th += loff; Tl += loff;
    int n0 = blockIdx.x * 32, k0 = blockIdx.y * 32;
    int tx = threadIdx.x, ty = threadIdx.y;          // 32 x 8
    #pragma unroll
    for (int i = 0; i < 4; i++)
        tile[ty + 8 * i][tx] = W[(long long)(k0 + ty + 8 * i) * N + n0 + tx];
    __syncthreads();
    #pragma unroll
    for (int i = 0; i < 4; i++) {
        float v = tile[tx][ty + 8 * i];
        bf16 h, l; split_bf16(v, h, l);
        long long o = (long long)(n0 + ty + 8 * i) * K + k0 + tx;
        Th[o] = h; Tl[o] = l;
    }
}

#define MMA_BF16(c, a0,a1,a2,a3, b0,b1)                                          \
    asm volatile("mma.sync.aligned.m16n8k16.row.col.f32.bf16.bf16.f32 "          \
                 "{%0,%1,%2,%3}, {%4,%5,%6,%7}, {%8,%9}, {%0,%1,%2,%3};"         \
                 : "+f"(c[0]), "+f"(c[1]), "+f"(c[2]), "+f"(c[3])                \
                 : "r"(a0), "r"(a1), "r"(a2), "r"(a3), "r"(b0), "r"(b1))

// ---------------- tensor-core GEMM (bf16 hi/lo triple, fp32 acc) ----------------
// Double-buffered cp.async pipeline, 256 threads, warp grid 2(M)x4(N).
// C[m][n] = scale * sum_k A[m][k]*B[n][k]  (+bias[n]) (relu?)  -- B given as [N][K]
// OUT: 0 = fp32 C, 1 = bf16 hi/lo C, 2 = transposed bf16 hi/lo C (C[n][m])
template<int BM, int BN, int OUT, bool RELU>
__global__ __launch_bounds__(256) void gemm_k(
    const bf16* __restrict__ Ah, const bf16* __restrict__ Al,
    long long lda, long long sAb, long long sAh,
    const bf16* __restrict__ Bh, const bf16* __restrict__ Bl,
    long long ldb, long long sBb, long long sBh,
    float* __restrict__ Cf, bf16* __restrict__ Ch, bf16* __restrict__ Cl,
    long long ldc, long long sCb, long long sCh,
    const float* __restrict__ bias, float scale, int K, int nh)
{
    extern __shared__ uint32_t sm[];
    const int AW = BM * 20, BW = BN * 20;
    const int SS = 2 * AW + 2 * BW;                    // words per stage

    int z = blockIdx.z;
    int zb = z / nh, zh = z - zb * nh;
    Ah += zb * sAb + zh * sAh;  Al += zb * sAb + zh * sAh;
    Bh += zb * sBb + zh * sBh;  Bl += zb * sBb + zh * sBh;

    const int m0 = blockIdx.y * BM;
    const int n0 = blockIdx.x * BN;
    const int t = threadIdx.x;
    const int lane = t & 31, w = t >> 5;
    const int wm = w >> 2, wn = w & 3;                 // 2 x 4 warp grid
    const int WNW = BN / 4;
    const int NJ  = WNW / 8;

    const unsigned sb = (unsigned)__cvta_generic_to_shared(sm);

    float acc[4][BN / 32][4];
    #pragma unroll
    for (int i = 0; i < 4; i++)
        #pragma unroll
        for (int j = 0; j < BN / 32; j++)
            #pragma unroll
            for (int r = 0; r < 4; r++) acc[i][j][r] = 0.f;

    const int nk = K / 32;

    auto load_stage = [&](int ks, int st) {
        const unsigned base = sb + st * SS * 4;
        const int k0 = ks * 32;
        #pragma unroll
        for (int i = 0; i < (BM * 4) / 256; i++) {
            int id = i * 256 + t;
            int row = id >> 2, cb = id & 3;
            long long go = (long long)(m0 + row) * lda + k0 + cb * 8;
            unsigned so = row * 80 + cb * 16;
            cpasync16(base + so, Ah + go);
            cpasync16(base + AW * 4 + so, Al + go);
        }
        #pragma unroll
        for (int i = 0; i < (BN * 4) / 256; i++) {
            int id = i * 256 + t;
            int row = id >> 2, cb = id & 3;
            long long go = (long long)(n0 + row) * ldb + k0 + cb * 8;
            unsigned so = row * 80 + cb * 16;
            cpasync16(base + 2 * AW * 4 + so, Bh + go);
            cpasync16(base + (2 * AW + BW) * 4 + so, Bl + go);
        }
        asm volatile("cp.async.commit_group;");
    };

    load_stage(0, 0);

    for (int ks = 0; ks < nk; ks++) {
        if (ks + 1 < nk) {
            load_stage(ks + 1, (ks + 1) & 1);
            asm volatile("cp.async.wait_group 1;" ::: "memory");
        } else {
            asm volatile("cp.async.wait_group 0;" ::: "memory");
        }
        __syncthreads();

        const uint32_t* Ash = sm + (ks & 1) * SS;
        const uint32_t* Asl = Ash + AW;
        const uint32_t* Bsh = Ash + 2 * AW;
        const uint32_t* Bsl = Ash + 2 * AW + BW;

        #pragma unroll
        for (int s = 0; s < 2; s++) {
            const int kw = s * 8;
            uint32_t bh[BN / 32][2], bl[BN / 32][2];
            #pragma unroll
            for (int j = 0; j < NJ; j++) {
                int idx = (wn * WNW + j * 8 + (lane >> 2)) * 20 + kw + (lane & 3);
                bh[j][0] = Bsh[idx]; bh[j][1] = Bsh[idx + 4];
                bl[j][0] = Bsl[idx]; bl[j][1] = Bsl[idx + 4];
            }
            #pragma unroll
            for (int i = 0; i < 4; i++) {
                int idx = (wm * 64 + i * 16 + (lane >> 2)) * 20 + kw + (lane & 3);
                uint32_t ah0 = Ash[idx],       ah1 = Ash[idx + 160];
                uint32_t ah2 = Ash[idx + 4],   ah3 = Ash[idx + 164];
                uint32_t al0 = Asl[idx],       al1 = Asl[idx + 160];
                uint32_t al2 = Asl[idx + 4],   al3 = Asl[idx + 164];
                #pragma unroll
                for (int j = 0; j < NJ; j++) {
                    MMA_BF16(acc[i][j], ah0, ah1, ah2, ah3, bh[j][0], bh[j][1]);
                    MMA_BF16(acc[i][j], ah0, ah1, ah2, ah3, bl[j][0], bl[j][1]);
                    MMA_BF16(acc[i][j], al0, al1, al2, al3, bh[j][0], bh[j][1]);
                }
            }
        }
        __syncthreads();
    }

    float* CfB = Cf ? Cf + zb * sCb + zh * sCh : nullptr;
    bf16*  ChB = Ch ? Ch + zb * sCb + zh * sCh : nullptr;
    bf16*  ClB = Cl ? Cl + zb * sCb + zh * sCh : nullptr;

    #pragma unroll
    for (int i = 0; i < 4; i++) {
        int r0 = m0 + wm * 64 + i * 16 + (lane >> 2);
        int r1 = r0 + 8;
        #pragma unroll
        for (int j = 0; j < NJ; j++) {
            int n = n0 + wn * WNW + j * 8 + 2 * (lane & 3);
            float b0v = 0.f, b1v = 0.f;
            if (bias) { b0v = bias[n]; b1v = bias[n + 1]; }
            float v00 = acc[i][j][0] * scale + b0v;
            float v01 = acc[i][j][1] * scale + b1v;
            float v10 = acc[i][j][2] * scale + b0v;
            float v11 = acc[i][j][3] * scale + b1v;
            if (RELU) {
                v00 = fmaxf(v00, 0.f); v01 = fmaxf(v01, 0.f);
                v10 = fmaxf(v10, 0.f); v11 = fmaxf(v11, 0.f);
            }
            if (OUT == 0) {
                *(float2*)(CfB + (long long)r0 * ldc + n) = make_float2(v00, v01);
                *(float2*)(CfB + (long long)r1 * ldc + n) = make_float2(v10, v11);
            } else if (OUT == 1) {
                __nv_bfloat162 h, l;
                split_bf16(v00, h.x, l.x); split_bf16(v01, h.y, l.y);
                *(__nv_bfloat162*)(ChB + (long long)r0 * ldc + n) = h;
                *(__nv_bfloat162*)(ClB + (long long)r0 * ldc + n) = l;
                split_bf16(v10, h.x, l.x); split_bf16(v11, h.y, l.y);
                *(__nv_bfloat162*)(ChB + (long long)r1 * ldc + n) = h;
                *(__nv_bfloat162*)(ClB + (long long)r1 * ldc + n) = l;
            } else {
                bf16 h, l;
                split_bf16(v00, h, l); ChB[(long long)n * ldc + r0] = h; ClB[(long long)n * ldc + r0] = l;
                split_bf16(v01, h, l); ChB[(long long)(n + 1) * ldc + r0] = h; ClB[(long long)(n + 1) * ldc + r0] = l;
                split_bf16(v10, h, l); ChB[(long long)n * ldc + r1] = h; ClB[(long long)n * ldc + r1] = l;
                split_bf16(v11, h, l); ChB[(long long)(n + 1) * ldc + r1] = h; ClB[(long long)(n + 1) * ldc + r1] = l;
            }
        }
    }
}

#define GSMEM(BM, BN) ((2 * ((BM) * 20) + 2 * ((BN) * 20)) * 2 * 4)

// ---------------- fused flash attention ----------------
// Per CTA: one (b,h) and 64 Q rows. 4 warps x 16 rows. Bc=64 key tile, 16 tiles.
// S = (Q K^T)/8 via hi/lo triple mma; online softmax in registers; O += P V via
// hi/lo triple mma (P split in registers). Output -> bugged layout [b][h][s][d], bf16 hi/lo.
#define FQW (64 * 36)                 // words per Q matrix (64 rows x 36-word stride)
#define FMW (64 * 36)                 // words per K/V matrix
#define FSMEM ((2 * FQW + 8 * FMW) * 4)   // 92160 B

__global__ __launch_bounds__(128) void flash_k(
    const bf16* __restrict__ qh_, const bf16* __restrict__ ql_,
    const bf16* __restrict__ kh_, const bf16* __restrict__ kl_,
    const bf16* __restrict__ vTh_, const bf16* __restrict__ vTl_,
    bf16* __restrict__ oh_, bf16* __restrict__ ol_)
{
    extern __shared__ uint32_t sm[];
    const int qt = blockIdx.x;             // 0..15
    const int bh = blockIdx.y;             // 0..31  (= b*8 + h)
    const int b = bh >> 3, h = bh & 7;
    const int q0 = qt * 64;
    const int t = threadIdx.x, lane = t & 31, w = t >> 5;
    const unsigned sb = (unsigned)__cvta_generic_to_shared(sm);

    // ---- load Q tile (hi/lo) ----
    #pragma unroll
    for (int i = 0; i < 4; i++) {
        int id = i * 128 + t;
        int r = id >> 3, cb = id & 7;
        long long gq = ((long long)(b * SEQ + q0 + r)) * DMODEL + h * DHEAD + cb * 8;
        unsigned so = r * 144 + cb * 16;
        cpasync16(sb + so, qh_ + gq);
        cpasync16(sb + FQW * 4 + so, ql_ + gq);
    }
    asm volatile("cp.async.commit_group;");

    // ---- stage loader for K/V tiles ----
    auto load_stage = [&](int ti, int st) {
        const unsigned base = sb + (2 * FQW + st * 4 * FMW) * 4;
        const int t0 = ti * 64;
        #pragma unroll
        for (int i = 0; i < 4; i++) {
            int id = i * 128 + t;
            int r = id >> 3, cb = id & 7;
            unsigned so = r * 144 + cb * 16;
            long long gk = ((long long)(b * SEQ + t0 + r)) * DMODEL + h * DHEAD + cb * 8;
            cpasync16(base + so, kh_ + gk);
            cpasync16(base + FMW * 4 + so, kl_ + gk);
            long long gv = ((long long)(h * DHEAD + r)) * TOKENS + b * SEQ + t0 + cb * 8;
            cpasync16(base + 2 * FMW * 4 + so, vTh_ + gv);
            cpasync16(base + 3 * FMW * 4 + so, vTl_ + gv);
        }
        asm volatile("cp.async.commit_group;");
    };

    load_stage(0, 0);
    asm volatile("cp.async.wait_group 0;" ::: "memory");
    __syncthreads();

    // ---- read Q fragments into registers ----
    uint32_t qfh[4][4], qfl[4][4];
    {
        const uint32_t* Qh = sm;
        const uint32_t* Ql = sm + FQW;
        int rw = (w * 16 + (lane >> 2)) * 36;
        #pragma unroll
        for (int ks = 0; ks < 4; ks++) {
            int idx = rw + ks * 8 + (lane & 3);
            qfh[ks][0] = Qh[idx];       qfh[ks][1] = Qh[idx + 288];
            qfh[ks][2] = Qh[idx + 4];   qfh[ks][3] = Qh[idx + 292];
            qfl[ks][0] = Ql[idx];       qfl[ks][1] = Ql[idx + 288];
            qfl[ks][2] = Ql[idx + 4];   qfl[ks][3] = Ql[idx + 292];
        }
    }

    float acc_o[8][4];
    #pragma unroll
    for (int j = 0; j < 8; j++)
        #pragma unroll
        for (int r = 0; r < 4; r++) acc_o[j][r] = 0.f;
    float m0 = -1e30f, m1 = -1e30f, l0 = 0.f, l1 = 0.f;

    const int NT = SEQ / 64;   // 16

    for (int ti = 0; ti < NT; ti++) {
        if (ti + 1 < NT) load_stage(ti + 1, (ti + 1) & 1);

        const uint32_t* Kh = sm + 2 * FQW + (ti & 1) * 4 * FMW;
        const uint32_t* Kl = Kh + FMW;
        const uint32_t* Vh = Kh + 2 * FMW;
        const uint32_t* Vl = Kh + 3 * FMW;

        // ---- S = Q K^T (hi/lo triple) ----
        float s_[8][4];
        #pragma unroll
        for (int j = 0; j < 8; j++)
            #pragma unroll
            for (int r = 0; r < 4; r++) s_[j][r] = 0.f;

        #pragma unroll
        for (int ks = 0; ks < 4; ks++) {
            #pragma unroll
            for (int j = 0; j < 8; j++) {
                int bi = (j * 8 + (lane >> 2)) * 36 + ks * 8 + (lane & 3);
                uint32_t kb0 = Kh[bi], kb1 = Kh[bi + 4];
                uint32_t kl0 = Kl[bi], kl1 = Kl[bi + 4];
                MMA_BF16(s_[j], qfh[ks][0], qfh[ks][1], qfh[ks][2], qfh[ks][3], kb0, kb1);
                MMA_BF16(s_[j], qfh[ks][0], qfh[ks][1], qfh[ks][2], qfh[ks][3], kl0, kl1);
                MMA_BF16(s_[j], qfl[ks][0], qfl[ks][1], qfl[ks][2], qfl[ks][3], kb0, kb1);
            }
        }

        // ---- online softmax (rows r and r+8 per thread; reduce over lane&3) ----
        float tm0 = -1e30f, tm1 = -1e30f;
        #pragma unroll
        for (int j = 0; j < 8; j++) {
            s_[j][0] *= 0.125f; s_[j][1] *= 0.125f; s_[j][2] *= 0.125f; s_[j][3] *= 0.125f;
            tm0 = fmaxf(tm0, fmaxf(s_[j][0], s_[j][1]));
            tm1 = fmaxf(tm1, fmaxf(s_[j][2], s_[j][3]));
        }
        tm0 = fmaxf(tm0, __shfl_xor_sync(0xffffffffu, tm0, 1));
        tm0 = fmaxf(tm0, __shfl_xor_sync(0xffffffffu, tm0, 2));
        tm1 = fmaxf(tm1, __shfl_xor_sync(0xffffffffu, tm1, 1));
        tm1 = fmaxf(tm1, __shfl_xor_sync(0xffffffffu, tm1, 2));
        float mn0 = fmaxf(m0, tm0), mn1 = fmaxf(m1, tm1);
        float f0 = __expf(m0 - mn0), f1 = __expf(m1 - mn1);
        m0 = mn0; m1 = mn1;

        float sum0 = 0.f, sum1 = 0.f;
        #pragma unroll
        for (int j = 0; j < 8; j++) {
            s_[j][0] = __expf(s_[j][0] - mn0);
            s_[j][1] = __expf(s_[j][1] - mn0);
            s_[j][2] = __expf(s_[j][2] - mn1);
            s_[j][3] = __expf(s_[j][3] - mn1);
            sum0 += s_[j][0] + s_[j][1];
            sum1 += s_[j][2] + s_[j][3];
        }
        sum0 += __shfl_xor_sync(0xffffffffu, sum0, 1);
        sum0 += __shfl_xor_sync(0xffffffffu, sum0, 2);
        sum1 += __shfl_xor_sync(0xffffffffu, sum1, 1);
        sum1 += __shfl_xor_sync(0xffffffffu, sum1, 2);
        l0 = l0 * f0 + sum0;
        l1 = l1 * f1 + sum1;

        #pragma unroll
        for (int j = 0; j < 8; j++) {
            acc_o[j][0] *= f0; acc_o[j][1] *= f0;
            acc_o[j][2] *= f1; acc_o[j][3] *= f1;
        }

        // ---- O += P V (P split hi/lo in registers) ----
        #pragma unroll
        for (int ts = 0; ts < 4; ts++) {
            uint32_t pah[4], pal[4];
            #pragma unroll
            for (int half = 0; half < 2; half++) {
                const float* p = s_[2 * ts + half];
                __nv_bfloat162 h2, l2;
                split_bf16(p[0], h2.x, l2.x); split_bf16(p[1], h2.y, l2.y);
                pah[half ? 2 : 0] = *(uint32_t*)&h2;
                pal[half ? 2 : 0] = *(uint32_t*)&l2;
                split_bf16(p[2], h2.x, l2.x); split_bf16(p[3], h2.y, l2.y);
                pah[half ? 3 : 1] = *(uint32_t*)&h2;
                pal[half ? 3 : 1] = *(uint32_t*)&l2;
            }
            #pragma unroll
            for (int jd = 0; jd < 8; jd++) {
                int bi = (jd * 8 + (lane >> 2)) * 36 + ts * 8 + (lane & 3);
                uint32_t vb0 = Vh[bi], vb1 = Vh[bi + 4];
                uint32_t vl0 = Vl[bi], vl1 = Vl[bi + 4];
                MMA_BF16(acc_o[jd], pah[0], pah[1], pah[2], pah[3], vb0, vb1);
                MMA_BF16(acc_o[jd], pah[0], pah[1], pah[2], pah[3], vl0, vl1);
                MMA_BF16(acc_o[jd], pal[0], pal[1], pal[2], pal[3], vb0, vb1);
            }
        }

        if (ti + 1 < NT) { asm volatile("cp.async.wait_group 0;" ::: "memory"); }
        __syncthreads();
    }

    // ---- epilogue: normalize, split hi/lo, store in bugged layout ----
    float i0 = 1.f / l0, i1 = 1.f / l1;
    int r0 = q0 + w * 16 + (lane >> 2);
    int r1 = r0 + 8;
    long long base0 = ((long long)bh * SEQ + r0) * DHEAD;
    long long base1 = ((long long)bh * SEQ + r1) * DHEAD;
    #pragma unroll
    for (int jd = 0; jd < 8; jd++) {
        int c = jd * 8 + 2 * (lane & 3);
        __nv_bfloat162 h2, l2;
        split_bf16(acc_o[jd][0] * i0, h2.x, l2.x);
        split_bf16(acc_o[jd][1] * i0, h2.y, l2.y);
        *(__nv_bfloat162*)(oh_ + base0 + c) = h2;
        *(__nv_bfloat162*)(ol_ + base0 + c) = l2;
        split_bf16(acc_o[jd][2] * i1, h2.x, l2.x);
        split_bf16(acc_o[jd][3] * i1, h2.y, l2.y);
        *(__nv_bfloat162*)(oh_ + base1 + c) = h2;
        *(__nv_bfloat162*)(ol_ + base1 + c) = l2;
    }
}

// ---------------- fused residual add + LayerNorm (optionally emits hi/lo) ----------
template<bool WH>
__global__ void addln_k(const float* __restrict__ a, const float* __restrict__ b,
                        const float* __restrict__ g, const float* __restrict__ be,
                        float* __restrict__ o, bf16* __restrict__ oh, bf16* __restrict__ ol) {
    long long row = blockIdx.x;
    int t = threadIdx.x;
    float4 av = *(const float4*)(a + row * DMODEL + t * 4);
    float4 bv = *(const float4*)(b + row * DMODEL + t * 4);
    float x0 = av.x + bv.x, x1 = av.y + bv.y, x2 = av.z + bv.z, x3 = av.w + bv.w;
    float m = block_sum(x0 + x1 + x2 + x3) * (1.f / DMODEL);
    float d0 = x0 - m, d1 = x1 - m, d2 = x2 - m, d3 = x3 - m;
    float var = block_sum(d0 * d0 + d1 * d1 + d2 * d2 + d3 * d3) * (1.f / DMODEL);
    float r = rsqrtf(var + LN_EPS);
    float4 gv = *(const float4*)(g + t * 4);
    float4 ev = *(const float4*)(be + t * 4);
    float4 ov;
    ov.x = d0 * r * gv.x + ev.x;
    ov.y = d1 * r * gv.y + ev.y;
    ov.z = d2 * r * gv.z + ev.z;
    ov.w = d3 * r * gv.w + ev.w;
    *(float4*)(o + row * DMODEL + t * 4) = ov;
    if (WH) {
        __nv_bfloat162 h0, l0, h1, l1;
        split_bf16(ov.x, h0.x, l0.x); split_bf16(ov.y, h0.y, l0.y);
        split_bf16(ov.z, h1.x, l1.x); split_bf16(ov.w, h1.y, l1.y);
        long long off = row * DMODEL + t * 4;
        *(__nv_bfloat162*)(oh + off) = h0; *(__nv_bfloat162*)(oh + off + 2) = h1;
        *(__nv_bfloat162*)(ol + off) = l0; *(__nv_bfloat162*)(ol + off + 2) = l1;
    }
}

// ---------------- launch ----------------
extern "C" void kernel_launch(void* const* d_in, const int* in_sizes, int n_in,
                              void* d_out, int out_size)
{
    const int*   tok = (const int*)d_in[0];
    const float* emb = (const float*)d_in[1];
    const float* Wq = (const float*)d_in[2],  *bq = (const float*)d_in[3];
    const float* Wk = (const float*)d_in[4],  *bk = (const float*)d_in[5];
    const float* Wv = (const float*)d_in[6],  *bv = (const float*)d_in[7];
    const float* Wo = (const float*)d_in[8],  *bo = (const float*)d_in[9];
    const float* W1 = (const float*)d_in[10], *b1 = (const float*)d_in[11];
    const float* W2 = (const float*)d_in[12], *b2 = (const float*)d_in[13];
    const float* lg = (const float*)d_in[14], *lb = (const float*)d_in[15];
    float* out = (float*)d_out;

    float *x, *y;
    bf16 *xh, *xl, *qh, *ql, *kh, *kl, *vTh, *vTl, *ah, *al, *h1h, *h1l;
    bf16 *wqTh, *wqTl, *wkTh, *wkTl, *wvTh, *wvTl, *woTh, *woTl, *w1Th, *w1Tl, *w2Th, *w2Tl;
    cudaGetSymbolAddress((void**)&x,   g_x);
    cudaGetSymbolAddress((void**)&y,   g_y);
    cudaGetSymbolAddress((void**)&xh,  g_xh);   cudaGetSymbolAddress((void**)&xl,  g_xl);
    cudaGetSymbolAddress((void**)&qh,  g_qh);   cudaGetSymbolAddress((void**)&ql,  g_ql);
    cudaGetSymbolAddress((void**)&kh,  g_kh);   cudaGetSymbolAddress((void**)&kl,  g_kl);
    cudaGetSymbolAddress((void**)&vTh, g_vTh);  cudaGetSymbolAddress((void**)&vTl, g_vTl);
    cudaGetSymbolAddress((void**)&ah,  g_ah);   cudaGetSymbolAddress((void**)&al,  g_al);
    cudaGetSymbolAddress((void**)&h1h, g_h1h);  cudaGetSymbolAddress((void**)&h1l, g_h1l);
    cudaGetSymbolAddress((void**)&wqTh, g_wqTh); cudaGetSymbolAddress((void**)&wqTl, g_wqTl);
    cudaGetSymbolAddress((void**)&wkTh, g_wkTh); cudaGetSymbolAddress((void**)&wkTl, g_wkTl);
    cudaGetSymbolAddress((void**)&wvTh, g_wvTh); cudaGetSymbolAddress((void**)&wvTl, g_wvTl);
    cudaGetSymbolAddress((void**)&woTh, g_woTh); cudaGetSymbolAddress((void**)&woTl, g_woTl);
    cudaGetSymbolAddress((void**)&w1Th, g_w1Th); cudaGetSymbolAddress((void**)&w1Tl, g_w1Tl);
    cudaGetSymbolAddress((void**)&w2Th, g_w2Th); cudaGetSymbolAddress((void**)&w2Tl, g_w2Tl);

    cudaFuncSetAttribute(gemm_k<128,128,0,false>, cudaFuncAttributeMaxDynamicSharedMemorySize, GSMEM(128,128));
    cudaFuncSetAttribute(gemm_k<128,128,1,false>, cudaFuncAttributeMaxDynamicSharedMemorySize, GSMEM(128,128));
    cudaFuncSetAttribute(gemm_k<128,128,2,false>, cudaFuncAttributeMaxDynamicSharedMemorySize, GSMEM(128,128));
    cudaFuncSetAttribute(gemm_k<128,128,1,true >, cudaFuncAttributeMaxDynamicSharedMemorySize, GSMEM(128,128));
    cudaFuncSetAttribute(flash_k, cudaFuncAttributeMaxDynamicSharedMemorySize, FSMEM);

    // ---- convert + transpose all weights (batched over layers) ----
    dim3 cb(32, 8);
    wconv_k<<<dim3(16, 16, NLAYERS), cb>>>(Wq, wqTh, wqTl, DMODEL, DMODEL);
    wconv_k<<<dim3(16, 16, NLAYERS), cb>>>(Wk, wkTh, wkTl, DMODEL, DMODEL);
    wconv_k<<<dim3(16, 16, NLAYERS), cb>>>(Wv, wvTh, wvTl, DMODEL, DMODEL);
    wconv_k<<<dim3(16, 16, NLAYERS), cb>>>(Wo, woTh, woTl, DMODEL, DMODEL);
    wconv_k<<<dim3(64, 16, NLAYERS), cb>>>(W1, w1Th, w1Tl, DFF, DMODEL);
    wconv_k<<<dim3(16, 64, NLAYERS), cb>>>(W2, w2Th, w2Tl, DMODEL, DFF);

    embed_k<<<TOKENS, 128>>>(tok, emb, x, xh, xl);

    const int S128 = GSMEM(128,128);

    for (int i = 0; i < NLAYERS; i++) {
        long long woff = (long long)i * DMODEL * DMODEL;
        long long foff = (long long)i * DMODEL * DFF;
        const float* bqi = bq + (long long)i * DMODEL;
        const float* bki = bk + (long long)i * DMODEL;
        const float* bvi = bv + (long long)i * DMODEL;
        const float* boi = bo + (long long)i * DMODEL;
        const float* b1i = b1 + (long long)i * DFF;
        const float* b2i = b2 + (long long)i * DMODEL;
        const float* lgi = lg + (long long)i * DMODEL;
        const float* lbi = lb + (long long)i * DMODEL;

        // Q, K projections -> bf16 hi/lo [4096][512]
        gemm_k<128,128,1,false><<<dim3(4, 32, 1), 256, S128>>>(
            xh, xl, DMODEL, 0, 0, wqTh + woff, wqTl + woff, DMODEL, 0, 0,
            nullptr, qh, ql, DMODEL, 0, 0, bqi, 1.f, DMODEL, 1);
        gemm_k<128,128,1,false><<<dim3(4, 32, 1), 256, S128>>>(
            xh, xl, DMODEL, 0, 0, wkTh + woff, wkTl + woff, DMODEL, 0, 0,
            nullptr, kh, kl, DMODEL, 0, 0, bki, 1.f, DMODEL, 1);
        // V projection -> transposed bf16 hi/lo [512][4096]
        gemm_k<128,128,2,false><<<dim3(4, 32, 1), 256, S128>>>(
            xh, xl, DMODEL, 0, 0, wvTh + woff, wvTl + woff, DMODEL, 0, 0,
            nullptr, vTh, vTl, TOKENS, 0, 0, bvi, 1.f, DMODEL, 1);

        // fused attention -> bf16 hi/lo attn in bugged layout
        flash_k<<<dim3(16, 32), 128, FSMEM>>>(qh, ql, kh, kl, vTh, vTl, ah, al);

        // O projection (bugged-layout attn viewed [4096][512]) -> fp32 y
        gemm_k<128,128,0,false><<<dim3(4, 32, 1), 256, S128>>>(
            ah, al, DMODEL, 0, 0, woTh + woff, woTl + woff, DMODEL, 0, 0,
            y, nullptr, nullptr, DMODEL, 0, 0, boi, 1.f, DMODEL, 1);

        addln_k<true><<<TOKENS, 128>>>(x, y, lgi, lbi, x, xh, xl);

        // FFN1 (relu) -> bf16 hi/lo [4096][2048]
        gemm_k<128,128,1,true><<<dim3(16, 32, 1), 256, S128>>>(
            xh, xl, DMODEL, 0, 0, w1Th + foff, w1Tl + foff, DMODEL, 0, 0,
            nullptr, h1h, h1l, DFF, 0, 0, b1i, 1.f, DMODEL, 1);
        // FFN2 -> fp32 y
        gemm_k<128,128,0,false><<<dim3(4, 32, 1), 256, S128>>>(
            h1h, h1l, DFF, 0, 0, w2Th + foff, w2Tl + foff, DFF, 0, 0,
            y, nullptr, nullptr, DMODEL, 0, 0, b2i, 1.f, DFF, 1);

        if (i == NLAYERS - 1)
            addln_k<false><<<TOKENS, 128>>>(x, y, lgi, lbi, out, nullptr, nullptr);
        else
            addln_k<true><<<TOKENS, 128>>>(x, y, lgi, lbi, x, xh, xl);
    }
}

// round 6
// speedup vs baseline: 4.4318x; 1.0678x over previous
#include <cuda_runtime.h>
#include <cuda_bf16.h>
#include <math.h>
#include <cstdint>

#define NLAYERS 6
#define DMODEL  512
#define NHEADS  8
#define DHEAD   64
#define BATCH   4
#define SEQ     1024
#define TOKENS  (BATCH*SEQ)      // 4096
#define DFF     2048
#define LN_EPS  1e-5f
#define NQKV    (3*DMODEL)       // 1536

typedef __nv_bfloat16 bf16;

// ---------------- scratch (device globals; no allocation allowed) ----------------
__device__ __align__(16) float g_x  [TOKENS*DMODEL];
__device__ __align__(16) float g_y  [TOKENS*DMODEL];

__device__ __align__(16) bf16 g_xh[TOKENS*DMODEL],  g_xl[TOKENS*DMODEL];
__device__ __align__(16) bf16 g_qh[TOKENS*DMODEL],  g_ql[TOKENS*DMODEL];
__device__ __align__(16) bf16 g_kh[TOKENS*DMODEL],  g_kl[TOKENS*DMODEL];
__device__ __align__(16) bf16 g_vTh[TOKENS*DMODEL], g_vTl[TOKENS*DMODEL];   // [512][4096]
__device__ __align__(16) bf16 g_ah[TOKENS*DMODEL],  g_al[TOKENS*DMODEL];
__device__ __align__(16) bf16 g_h1h[TOKENS*DFF],    g_h1l[TOKENS*DFF];

// transposed bf16 weights
__device__ __align__(16) bf16 g_wqkvTh[NLAYERS*NQKV*DMODEL], g_wqkvTl[NLAYERS*NQKV*DMODEL];
__device__ __align__(16) bf16 g_woTh[NLAYERS*DMODEL*DMODEL], g_woTl[NLAYERS*DMODEL*DMODEL];
__device__ __align__(16) bf16 g_w1Th[NLAYERS*DMODEL*DFF],    g_w1Tl[NLAYERS*DMODEL*DFF];
__device__ __align__(16) bf16 g_w2Th[NLAYERS*DMODEL*DFF],    g_w2Tl[NLAYERS*DMODEL*DFF];
__device__ __align__(16) float g_bqkv[NLAYERS*NQKV];

// ---------------- helpers ----------------
__device__ __forceinline__ void split_bf16(float v, bf16& h, bf16& l) {
    h = __float2bfloat16_rn(v);
    l = __float2bfloat16_rn(v - __bfloat162float(h));
}

__device__ __forceinline__ void cpasync16(unsigned saddr, const void* g) {
    asm volatile("cp.async.cg.shared.global [%0], [%1], 16;\n" :: "r"(saddr), "l"(g));
}

__device__ __forceinline__ float block_sum(float v) {
    __shared__ float s[32];
    #pragma unroll
    for (int o = 16; o; o >>= 1) v += __shfl_xor_sync(0xffffffffu, v, o);
    int lane = threadIdx.x & 31, w = threadIdx.x >> 5;
    if (lane == 0) s[w] = v;
    __syncthreads();
    int nw = blockDim.x >> 5;
    v = (threadIdx.x < (unsigned)nw) ? s[threadIdx.x] : 0.f;
    if (w == 0) {
        #pragma unroll
        for (int o = 16; o; o >>= 1) v += __shfl_xor_sync(0xffffffffu, v, o);
        if (lane == 0) s[0] = v;
    }
    __syncthreads();
    v = s[0];
    __syncthreads();
    return v;
}

// ---------------- embedding + positional encoding (+hi/lo) ----------------
__global__ void embed_k(const int* __restrict__ tok, const float* __restrict__ emb,
                        float* __restrict__ x, bf16* __restrict__ xh, bf16* __restrict__ xl) {
    long long row = blockIdx.x;
    int s = (int)(row & (SEQ - 1));
    int tk = tok[row];
    int t = threadIdx.x;
    #pragma unroll
    for (int j = 0; j < 4; j++) {
        int i = t * 4 + j;
        float freq = (float)exp(-(double)i * (9.210340371976184 / (double)DMODEL));
        float ang = (float)s * freq;
        float pe = (i & 1) ? cosf(ang) : sinf(ang);
        float v = emb[(long long)tk * DMODEL + i] + pe;
        x[row * DMODEL + i] = v;
        bf16 h, l; split_bf16(v, h, l);
        xh[row * DMODEL + i] = h;
        xl[row * DMODEL + i] = l;
    }
}

// ------- weight transpose + bf16 split: W[K][N] -> T[N][K], batched over layers -------
// separate source stride (N*K) and dest stride (for packing QKV into one buffer)
__global__ void wconv_k(const float* __restrict__ W, bf16* __restrict__ Th,
                        bf16* __restrict__ Tl, int N, int K,
                        long long wstride, long long dstride) {
    __shared__ float tile[32][33];
    W  += (long long)blockIdx.z * wstride;
    Th += (long long)blockIdx.z * dstride;
    Tl += (long long)blockIdx.z * dstride;
    int n0 = blockIdx.x * 32, k0 = blockIdx.y * 32;
    int tx = threadIdx.x, ty = threadIdx.y;          // 32 x 8
    #pragma unroll
    for (int i = 0; i < 4; i++)
        tile[ty + 8 * i][tx] = W[(long long)(k0 + ty + 8 * i) * N + n0 + tx];
    __syncthreads();
    #pragma unroll
    for (int i = 0; i < 4; i++) {
        float v = tile[tx][ty + 8 * i];
        bf16 h, l; split_bf16(v, h, l);
        long long o = (long long)(n0 + ty + 8 * i) * K + k0 + tx;
        Th[o] = h; Tl[o] = l;
    }
}

// ---- merge q,k,v biases into one [1536] per layer ----
__global__ void bmerge_k(const float* __restrict__ bq, const float* __restrict__ bk,
                         const float* __restrict__ bv, float* __restrict__ o) {
    int l = blockIdx.x, t = threadIdx.x;   // 512 threads
    o[l * NQKV + t]            = bq[l * DMODEL + t];
    o[l * NQKV + DMODEL + t]   = bk[l * DMODEL + t];
    o[l * NQKV + 2*DMODEL + t] = bv[l * DMODEL + t];
}

#define MMA_BF16(c, a0,a1,a2,a3, b0,b1)                                          \
    asm volatile("mma.sync.aligned.m16n8k16.row.col.f32.bf16.bf16.f32 "          \
                 "{%0,%1,%2,%3}, {%4,%5,%6,%7}, {%8,%9}, {%0,%1,%2,%3};"         \
                 : "+f"(c[0]), "+f"(c[1]), "+f"(c[2]), "+f"(c[3])                \
                 : "r"(a0), "r"(a1), "r"(a2), "r"(a3), "r"(b0), "r"(b1))

// ---------------- tensor-core GEMM (bf16 hi/lo triple, fp32 acc) ----------------
// 128 threads, 4 warps, 2x2 warp grid, warp tile 64x64. Double-buffered cp.async.
// C[m][n] = scale * sum_k A[m][k]*B[n][k]  (+bias[n]) (relu?)  -- B given as [N][K]
// OUT: 0 = fp32 C; 1 = bf16 hi/lo C (Ch/Cl, ldc);
//      3 = QKV: seg(n>>9) 0->Ch/Cl [m][512], 1->Dh/Dl [m][512], 2->Eh/El transposed [n][4096]
template<int BM, int BN, int OUT, bool RELU>
__global__ __launch_bounds__(128) void gemm_k(
    const bf16* __restrict__ Ah, const bf16* __restrict__ Al, long long lda,
    const bf16* __restrict__ Bh, const bf16* __restrict__ Bl, long long ldb,
    float* __restrict__ Cf, bf16* __restrict__ Ch, bf16* __restrict__ Cl,
    bf16* __restrict__ Dh, bf16* __restrict__ Dl,
    bf16* __restrict__ Eh, bf16* __restrict__ El,
    long long ldc, const float* __restrict__ bias, float scale, int K)
{
    extern __shared__ uint32_t sm[];
    const int AW = BM * 20, BW = BN * 20;
    const int SS = 2 * AW + 2 * BW;                    // words per stage

    const int m0 = blockIdx.y * BM;
    const int n0 = blockIdx.x * BN;
    const int t = threadIdx.x;
    const int lane = t & 31, w = t >> 5;
    const int wm = w >> 1, wn = w & 1;                 // 2 x 2 warp grid
    const int NJ = BN / 16;                            // 8 for BN=128

    const unsigned sb = (unsigned)__cvta_generic_to_shared(sm);

    float acc[4][BN / 16][4];
    #pragma unroll
    for (int i = 0; i < 4; i++)
        #pragma unroll
        for (int j = 0; j < NJ; j++)
            #pragma unroll
            for (int r = 0; r < 4; r++) acc[i][j][r] = 0.f;

    const int nk = K / 32;

    auto load_stage = [&](int ks, int st) {
        const unsigned base = sb + st * SS * 4;
        const int k0 = ks * 32;
        #pragma unroll
        for (int i = 0; i < (BM * 4) / 128; i++) {
            int id = i * 128 + t;
            int row = id >> 2, cb = id & 3;
            long long go = (long long)(m0 + row) * lda + k0 + cb * 8;
            unsigned so = row * 80 + cb * 16;
            cpasync16(base + so, Ah + go);
            cpasync16(base + AW * 4 + so, Al + go);
        }
        #pragma unroll
        for (int i = 0; i < (BN * 4) / 128; i++) {
            int id = i * 128 + t;
            int row = id >> 2, cb = id & 3;
            long long go = (long long)(n0 + row) * ldb + k0 + cb * 8;
            unsigned so = row * 80 + cb * 16;
            cpasync16(base + 2 * AW * 4 + so, Bh + go);
            cpasync16(base + (2 * AW + BW) * 4 + so, Bl + go);
        }
        asm volatile("cp.async.commit_group;");
    };

    load_stage(0, 0);

    for (int ks = 0; ks < nk; ks++) {
        if (ks + 1 < nk) {
            load_stage(ks + 1, (ks + 1) & 1);
            asm volatile("cp.async.wait_group 1;" ::: "memory");
        } else {
            asm volatile("cp.async.wait_group 0;" ::: "memory");
        }
        __syncthreads();

        const uint32_t* Ash = sm + (ks & 1) * SS;
        const uint32_t* Asl = Ash + AW;
        const uint32_t* Bsh = Ash + 2 * AW;
        const uint32_t* Bsl = Ash + 2 * AW + BW;

        #pragma unroll
        for (int s = 0; s < 2; s++) {
            const int kw = s * 8;
            uint32_t bh[BN / 16][2], bl[BN / 16][2];
            #pragma unroll
            for (int j = 0; j < NJ; j++) {
                int idx = (wn * (BN / 2) + j * 8 + (lane >> 2)) * 20 + kw + (lane & 3);
                bh[j][0] = Bsh[idx]; bh[j][1] = Bsh[idx + 4];
                bl[j][0] = Bsl[idx]; bl[j][1] = Bsl[idx + 4];
            }
            #pragma unroll
            for (int i = 0; i < 4; i++) {
                int idx = (wm * 64 + i * 16 + (lane >> 2)) * 20 + kw + (lane & 3);
                uint32_t ah0 = Ash[idx],       ah1 = Ash[idx + 160];
                uint32_t ah2 = Ash[idx + 4],   ah3 = Ash[idx + 164];
                uint32_t al0 = Asl[idx],       al1 = Asl[idx + 160];
                uint32_t al2 = Asl[idx + 4],   al3 = Asl[idx + 164];
                #pragma unroll
                for (int j = 0; j < NJ; j++) {
                    MMA_BF16(acc[i][j], ah0, ah1, ah2, ah3, bh[j][0], bh[j][1]);
                    MMA_BF16(acc[i][j], ah0, ah1, ah2, ah3, bl[j][0], bl[j][1]);
                    MMA_BF16(acc[i][j], al0, al1, al2, al3, bh[j][0], bh[j][1]);
                }
            }
        }
        __syncthreads();
    }

    // ---- epilogue ----
    int seg = 0;
    bf16 *Xh = Ch, *Xl = Cl;
    if (OUT == 3) {
        seg = n0 >> 9;
        Xh = (seg == 0) ? Ch : (seg == 1) ? Dh : Eh;
        Xl = (seg == 0) ? Cl : (seg == 1) ? Dl : El;
    }

    #pragma unroll
    for (int i = 0; i < 4; i++) {
        int r0 = m0 + wm * 64 + i * 16 + (lane >> 2);
        int r1 = r0 + 8;
        #pragma unroll
        for (int j = 0; j < NJ; j++) {
            int n = n0 + wn * (BN / 2) + j * 8 + 2 * (lane & 3);
            float b0v = 0.f, b1v = 0.f;
            if (bias) { b0v = bias[n]; b1v = bias[n + 1]; }
            float v00 = acc[i][j][0] * scale + b0v;
            float v01 = acc[i][j][1] * scale + b1v;
            float v10 = acc[i][j][2] * scale + b0v;
            float v11 = acc[i][j][3] * scale + b1v;
            if (RELU) {
                v00 = fmaxf(v00, 0.f); v01 = fmaxf(v01, 0.f);
                v10 = fmaxf(v10, 0.f); v11 = fmaxf(v11, 0.f);
            }
            if (OUT == 0) {
                *(float2*)(Cf + (long long)r0 * ldc + n) = make_float2(v00, v01);
                *(float2*)(Cf + (long long)r1 * ldc + n) = make_float2(v10, v11);
            } else if (OUT == 1) {
                __nv_bfloat162 h, l;
                split_bf16(v00, h.x, l.x); split_bf16(v01, h.y, l.y);
                *(__nv_bfloat162*)(Ch + (long long)r0 * ldc + n) = h;
                *(__nv_bfloat162*)(Cl + (long long)r0 * ldc + n) = l;
                split_bf16(v10, h.x, l.x); split_bf16(v11, h.y, l.y);
                *(__nv_bfloat162*)(Ch + (long long)r1 * ldc + n) = h;
                *(__nv_bfloat162*)(Cl + (long long)r1 * ldc + n) = l;
            } else { // OUT == 3
                int nl = n & 511;
                if (seg < 2) {
                    __nv_bfloat162 h, l;
                    split_bf16(v00, h.x, l.x); split_bf16(v01, h.y, l.y);
                    *(__nv_bfloat162*)(Xh + (long long)r0 * DMODEL + nl) = h;
                    *(__nv_bfloat162*)(Xl + (long long)r0 * DMODEL + nl) = l;
                    split_bf16(v10, h.x, l.x); split_bf16(v11, h.y, l.y);
                    *(__nv_bfloat162*)(Xh + (long long)r1 * DMODEL + nl) = h;
                    *(__nv_bfloat162*)(Xl + (long long)r1 * DMODEL + nl) = l;
                } else {
                    bf16 h, l;
                    split_bf16(v00, h, l); Xh[(long long)nl * TOKENS + r0] = h; Xl[(long long)nl * TOKENS + r0] = l;
                    split_bf16(v01, h, l); Xh[(long long)(nl + 1) * TOKENS + r0] = h; Xl[(long long)(nl + 1) * TOKENS + r0] = l;
                    split_bf16(v10, h, l); Xh[(long long)nl * TOKENS + r1] = h; Xl[(long long)nl * TOKENS + r1] = l;
                    split_bf16(v11, h, l); Xh[(long long)(nl + 1) * TOKENS + r1] = h; Xl[(long long)(nl + 1) * TOKENS + r1] = l;
                }
            }
        }
    }
}

#define GSMEM(BM, BN) ((2 * ((BM) * 20) + 2 * ((BN) * 20)) * 2 * 4)

// ---------------- fused flash attention ----------------
#define FQW (64 * 36)
#define FMW (64 * 36)
#define FSMEM ((2 * FQW + 8 * FMW) * 4)   // 92160 B

__global__ __launch_bounds__(128) void flash_k(
    const bf16* __restrict__ qh_, const bf16* __restrict__ ql_,
    const bf16* __restrict__ kh_, const bf16* __restrict__ kl_,
    const bf16* __restrict__ vTh_, const bf16* __restrict__ vTl_,
    bf16* __restrict__ oh_, bf16* __restrict__ ol_)
{
    extern __shared__ uint32_t sm[];
    const int qt = blockIdx.x;
    const int bh = blockIdx.y;
    const int b = bh >> 3, h = bh & 7;
    const int q0 = qt * 64;
    const int t = threadIdx.x, lane = t & 31, w = t >> 5;
    const unsigned sb = (unsigned)__cvta_generic_to_shared(sm);

    #pragma unroll
    for (int i = 0; i < 4; i++) {
        int id = i * 128 + t;
        int r = id >> 3, cb = id & 7;
        long long gq = ((long long)(b * SEQ + q0 + r)) * DMODEL + h * DHEAD + cb * 8;
        unsigned so = r * 144 + cb * 16;
        cpasync16(sb + so, qh_ + gq);
        cpasync16(sb + FQW * 4 + so, ql_ + gq);
    }
    asm volatile("cp.async.commit_group;");

    auto load_stage = [&](int ti, int st) {
        const unsigned base = sb + (2 * FQW + st * 4 * FMW) * 4;
        const int t0 = ti * 64;
        #pragma unroll
        for (int i = 0; i < 4; i++) {
            int id = i * 128 + t;
            int r = id >> 3, cb = id & 7;
            unsigned so = r * 144 + cb * 16;
            long long gk = ((long long)(b * SEQ + t0 + r)) * DMODEL + h * DHEAD + cb * 8;
            cpasync16(base + so, kh_ + gk);
            cpasync16(base + FMW * 4 + so, kl_ + gk);
            long long gv = ((long long)(h * DHEAD + r)) * TOKENS + b * SEQ + t0 + cb * 8;
            cpasync16(base + 2 * FMW * 4 + so, vTh_ + gv);
            cpasync16(base + 3 * FMW * 4 + so, vTl_ + gv);
        }
        asm volatile("cp.async.commit_group;");
    };

    load_stage(0, 0);
    asm volatile("cp.async.wait_group 0;" ::: "memory");
    __syncthreads();

    uint32_t qfh[4][4], qfl[4][4];
    {
        const uint32_t* Qh = sm;
        const uint32_t* Ql = sm + FQW;
        int rw = (w * 16 + (lane >> 2)) * 36;
        #pragma unroll
        for (int ks = 0; ks < 4; ks++) {
            int idx = rw + ks * 8 + (lane & 3);
            qfh[ks][0] = Qh[idx];       qfh[ks][1] = Qh[idx + 288];
            qfh[ks][2] = Qh[idx + 4];   qfh[ks][3] = Qh[idx + 292];
            qfl[ks][0] = Ql[idx];       qfl[ks][1] = Ql[idx + 288];
            qfl[ks][2] = Ql[idx + 4];   qfl[ks][3] = Ql[idx + 292];
        }
    }

    float acc_o[8][4];
    #pragma unroll
    for (int j = 0; j < 8; j++)
        #pragma unroll
        for (int r = 0; r < 4; r++) acc_o[j][r] = 0.f;
    float m0 = -1e30f, m1 = -1e30f, l0 = 0.f, l1 = 0.f;

    const int NT = SEQ / 64;

    for (int ti = 0; ti < NT; ti++) {
        if (ti + 1 < NT) load_stage(ti + 1, (ti + 1) & 1);

        const uint32_t* Kh = sm + 2 * FQW + (ti & 1) * 4 * FMW;
        const uint32_t* Kl = Kh + FMW;
        const uint32_t* Vh = Kh + 2 * FMW;
        const uint32_t* Vl = Kh + 3 * FMW;

        float s_[8][4];
        #pragma unroll
        for (int j = 0; j < 8; j++)
            #pragma unroll
            for (int r = 0; r < 4; r++) s_[j][r] = 0.f;

        #pragma unroll
        for (int ks = 0; ks < 4; ks++) {
            #pragma unroll
            for (int j = 0; j < 8; j++) {
                int bi = (j * 8 + (lane >> 2)) * 36 + ks * 8 + (lane & 3);
                uint32_t kb0 = Kh[bi], kb1 = Kh[bi + 4];
                uint32_t kl0 = Kl[bi], kl1 = Kl[bi + 4];
                MMA_BF16(s_[j], qfh[ks][0], qfh[ks][1], qfh[ks][2], qfh[ks][3], kb0, kb1);
                MMA_BF16(s_[j], qfh[ks][0], qfh[ks][1], qfh[ks][2], qfh[ks][3], kl0, kl1);
                MMA_BF16(s_[j], qfl[ks][0], qfl[ks][1], qfl[ks][2], qfl[ks][3], kb0, kb1);
            }
        }

        float tm0 = -1e30f, tm1 = -1e30f;
        #pragma unroll
        for (int j = 0; j < 8; j++) {
            s_[j][0] *= 0.125f; s_[j][1] *= 0.125f; s_[j][2] *= 0.125f; s_[j][3] *= 0.125f;
            tm0 = fmaxf(tm0, fmaxf(s_[j][0], s_[j][1]));
            tm1 = fmaxf(tm1, fmaxf(s_[j][2], s_[j][3]));
        }
        tm0 = fmaxf(tm0, __shfl_xor_sync(0xffffffffu, tm0, 1));
        tm0 = fmaxf(tm0, __shfl_xor_sync(0xffffffffu, tm0, 2));
        tm1 = fmaxf(tm1, __shfl_xor_sync(0xffffffffu, tm1, 1));
        tm1 = fmaxf(tm1, __shfl_xor_sync(0xffffffffu, tm1, 2));
        float mn0 = fmaxf(m0, tm0), mn1 = fmaxf(m1, tm1);
        float f0 = __expf(m0 - mn0), f1 = __expf(m1 - mn1);
        m0 = mn0; m1 = mn1;

        float sum0 = 0.f, sum1 = 0.f;
        #pragma unroll
        for (int j = 0; j < 8; j++) {
            s_[j][0] = __expf(s_[j][0] - mn0);
            s_[j][1] = __expf(s_[j][1] - mn0);
            s_[j][2] = __expf(s_[j][2] - mn1);
            s_[j][3] = __expf(s_[j][3] - mn1);
            sum0 += s_[j][0] + s_[j][1];
            sum1 += s_[j][2] + s_[j][3];
        }
        sum0 += __shfl_xor_sync(0xffffffffu, sum0, 1);
        sum0 += __shfl_xor_sync(0xffffffffu, sum0, 2);
        sum1 += __shfl_xor_sync(0xffffffffu, sum1, 1);
        sum1 += __shfl_xor_sync(0xffffffffu, sum1, 2);
        l0 = l0 * f0 + sum0;
        l1 = l1 * f1 + sum1;

        #pragma unroll
        for (int j = 0; j < 8; j++) {
            acc_o[j][0] *= f0; acc_o[j][1] *= f0;
            acc_o[j][2] *= f1; acc_o[j][3] *= f1;
        }

        #pragma unroll
        for (int ts = 0; ts < 4; ts++) {
            uint32_t pah[4], pal[4];
            #pragma unroll
            for (int half = 0; half < 2; half++) {
                const float* p = s_[2 * ts + half];
                __nv_bfloat162 h2, l2;
                split_bf16(p[0], h2.x, l2.x); split_bf16(p[1], h2.y, l2.y);
                pah[half ? 2 : 0] = *(uint32_t*)&h2;
                pal[half ? 2 : 0] = *(uint32_t*)&l2;
                split_bf16(p[2], h2.x, l2.x); split_bf16(p[3], h2.y, l2.y);
                pah[half ? 3 : 1] = *(uint32_t*)&h2;
                pal[half ? 3 : 1] = *(uint32_t*)&l2;
            }
            #pragma unroll
            for (int jd = 0; jd < 8; jd++) {
                int bi = (jd * 8 + (lane >> 2)) * 36 + ts * 8 + (lane & 3);
                uint32_t vb0 = Vh[bi], vb1 = Vh[bi + 4];
                uint32_t vl0 = Vl[bi], vl1 = Vl[bi + 4];
                MMA_BF16(acc_o[jd], pah[0], pah[1], pah[2], pah[3], vb0, vb1);
                MMA_BF16(acc_o[jd], pah[0], pah[1], pah[2], pah[3], vl0, vl1);
                MMA_BF16(acc_o[jd], pal[0], pal[1], pal[2], pal[3], vb0, vb1);
            }
        }

        if (ti + 1 < NT) { asm volatile("cp.async.wait_group 0;" ::: "memory"); }
        __syncthreads();
    }

    float i0 = 1.f / l0, i1 = 1.f / l1;
    int r0 = q0 + w * 16 + (lane >> 2);
    int r1 = r0 + 8;
    long long base0 = ((long long)bh * SEQ + r0) * DHEAD;
    long long base1 = ((long long)bh * SEQ + r1) * DHEAD;
    #pragma unroll
    for (int jd = 0; jd < 8; jd++) {
        int c = jd * 8 + 2 * (lane & 3);
        __nv_bfloat162 h2, l2;
        split_bf16(acc_o[jd][0] * i0, h2.x, l2.x);
        split_bf16(acc_o[jd][1] * i0, h2.y, l2.y);
        *(__nv_bfloat162*)(oh_ + base0 + c) = h2;
        *(__nv_bfloat162*)(ol_ + base0 + c) = l2;
        split_bf16(acc_o[jd][2] * i1, h2.x, l2.x);
        split_bf16(acc_o[jd][3] * i1, h2.y, l2.y);
        *(__nv_bfloat162*)(oh_ + base1 + c) = h2;
        *(__nv_bfloat162*)(ol_ + base1 + c) = l2;
    }
}

// ---------------- fused residual add + LayerNorm (optionally emits hi/lo) ----------
template<bool WH>
__global__ void addln_k(const float* __restrict__ a, const float* __restrict__ b,
                        const float* __restrict__ g, const float* __restrict__ be,
                        float* __restrict__ o, bf16* __restrict__ oh, bf16* __restrict__ ol) {
    long long row = blockIdx.x;
    int t = threadIdx.x;
    float4 av = *(const float4*)(a + row * DMODEL + t * 4);
    float4 bv = *(const float4*)(b + row * DMODEL + t * 4);
    float x0 = av.x + bv.x, x1 = av.y + bv.y, x2 = av.z + bv.z, x3 = av.w + bv.w;
    float m = block_sum(x0 + x1 + x2 + x3) * (1.f / DMODEL);
    float d0 = x0 - m, d1 = x1 - m, d2 = x2 - m, d3 = x3 - m;
    float var = block_sum(d0 * d0 + d1 * d1 + d2 * d2 + d3 * d3) * (1.f / DMODEL);
    float r = rsqrtf(var + LN_EPS);
    float4 gv = *(const float4*)(g + t * 4);
    float4 ev = *(const float4*)(be + t * 4);
    float4 ov;
    ov.x = d0 * r * gv.x + ev.x;
    ov.y = d1 * r * gv.y + ev.y;
    ov.z = d2 * r * gv.z + ev.z;
    ov.w = d3 * r * gv.w + ev.w;
    *(float4*)(o + row * DMODEL + t * 4) = ov;
    if (WH) {
        __nv_bfloat162 h0, l0, h1, l1;
        split_bf16(ov.x, h0.x, l0.x); split_bf16(ov.y, h0.y, l0.y);
        split_bf16(ov.z, h1.x, l1.x); split_bf16(ov.w, h1.y, l1.y);
        long long off = row * DMODEL + t * 4;
        *(__nv_bfloat162*)(oh + off) = h0; *(__nv_bfloat162*)(oh + off + 2) = h1;
        *(__nv_bfloat162*)(ol + off) = l0; *(__nv_bfloat162*)(ol + off + 2) = l1;
    }
}

// ---------------- launch ----------------
extern "C" void kernel_launch(void* const* d_in, const int* in_sizes, int n_in,
                              void* d_out, int out_size)
{
    const int*   tok = (const int*)d_in[0];
    const float* emb = (const float*)d_in[1];
    const float* Wq = (const float*)d_in[2],  *bq = (const float*)d_in[3];
    const float* Wk = (const float*)d_in[4],  *bk = (const float*)d_in[5];
    const float* Wv = (const float*)d_in[6],  *bv = (const float*)d_in[7];
    const float* Wo = (const float*)d_in[8],  *bo = (const float*)d_in[9];
    const float* W1 = (const float*)d_in[10], *b1 = (const float*)d_in[11];
    const float* W2 = (const float*)d_in[12], *b2 = (const float*)d_in[13];
    const float* lg = (const float*)d_in[14], *lb = (const float*)d_in[15];
    float* out = (float*)d_out;

    float *x, *y, *bqkv;
    bf16 *xh, *xl, *qh, *ql, *kh, *kl, *vTh, *vTl, *ah, *al, *h1h, *h1l;
    bf16 *wqkvTh, *wqkvTl, *woTh, *woTl, *w1Th, *w1Tl, *w2Th, *w2Tl;
    cudaGetSymbolAddress((void**)&x,   g_x);
    cudaGetSymbolAddress((void**)&y,   g_y);
    cudaGetSymbolAddress((void**)&bqkv, g_bqkv);
    cudaGetSymbolAddress((void**)&xh,  g_xh);   cudaGetSymbolAddress((void**)&xl,  g_xl);
    cudaGetSymbolAddress((void**)&qh,  g_qh);   cudaGetSymbolAddress((void**)&ql,  g_ql);
    cudaGetSymbolAddress((void**)&kh,  g_kh);   cudaGetSymbolAddress((void**)&kl,  g_kl);
    cudaGetSymbolAddress((void**)&vTh, g_vTh);  cudaGetSymbolAddress((void**)&vTl, g_vTl);
    cudaGetSymbolAddress((void**)&ah,  g_ah);   cudaGetSymbolAddress((void**)&al,  g_al);
    cudaGetSymbolAddress((void**)&h1h, g_h1h);  cudaGetSymbolAddress((void**)&h1l, g_h1l);
    cudaGetSymbolAddress((void**)&wqkvTh, g_wqkvTh); cudaGetSymbolAddress((void**)&wqkvTl, g_wqkvTl);
    cudaGetSymbolAddress((void**)&woTh, g_woTh); cudaGetSymbolAddress((void**)&woTl, g_woTl);
    cudaGetSymbolAddress((void**)&w1Th, g_w1Th); cudaGetSymbolAddress((void**)&w1Tl, g_w1Tl);
    cudaGetSymbolAddress((void**)&w2Th, g_w2Th); cudaGetSymbolAddress((void**)&w2Tl, g_w2Tl);

    cudaFuncSetAttribute(gemm_k<128,128,0,false>, cudaFuncAttributeMaxDynamicSharedMemorySize, GSMEM(128,128));
    cudaFuncSetAttribute(gemm_k<128,128,1,true >, cudaFuncAttributeMaxDynamicSharedMemorySize, GSMEM(128,128));
    cudaFuncSetAttribute(gemm_k<128,128,3,false>, cudaFuncAttributeMaxDynamicSharedMemorySize, GSMEM(128,128));
    cudaFuncSetAttribute(flash_k, cudaFuncAttributeMaxDynamicSharedMemorySize, FSMEM);

    // ---- weight conversion: QKV packed into one [1536][512] buffer per layer ----
    dim3 cb(32, 8);
    const long long WS = (long long)DMODEL * DMODEL;
    const long long QS = (long long)NQKV * DMODEL;
    wconv_k<<<dim3(16, 16, NLAYERS), cb>>>(Wq, wqkvTh,                 wqkvTl,                 DMODEL, DMODEL, WS, QS);
    wconv_k<<<dim3(16, 16, NLAYERS), cb>>>(Wk, wqkvTh + (long long)DMODEL*DMODEL, wqkvTl + (long long)DMODEL*DMODEL, DMODEL, DMODEL, WS, QS);
    wconv_k<<<dim3(16, 16, NLAYERS), cb>>>(Wv, wqkvTh + 2ll*DMODEL*DMODEL, wqkvTl + 2ll*DMODEL*DMODEL, DMODEL, DMODEL, WS, QS);
    wconv_k<<<dim3(16, 16, NLAYERS), cb>>>(Wo, woTh, woTl, DMODEL, DMODEL, WS, WS);
    wconv_k<<<dim3(64, 16, NLAYERS), cb>>>(W1, w1Th, w1Tl, DFF, DMODEL, (long long)DMODEL*DFF, (long long)DMODEL*DFF);
    wconv_k<<<dim3(16, 64, NLAYERS), cb>>>(W2, w2Th, w2Tl, DMODEL, DFF, (long long)DMODEL*DFF, (long long)DMODEL*DFF);
    bmerge_k<<<NLAYERS, DMODEL>>>(bq, bk, bv, bqkv);

    embed_k<<<TOKENS, 128>>>(tok, emb, x, xh, xl);

    const int S128 = GSMEM(128,128);

    for (int i = 0; i < NLAYERS; i++) {
        long long woff = (long long)i * DMODEL * DMODEL;
        long long qoff = (long long)i * NQKV * DMODEL;
        long long foff = (long long)i * DMODEL * DFF;
        const float* boi = bo + (long long)i * DMODEL;
        const float* b1i = b1 + (long long)i * DFF;
        const float* b2i = b2 + (long long)i * DMODEL;
        const float* lgi = lg + (long long)i * DMODEL;
        const float* lbi = lb + (long long)i * DMODEL;

        // merged QKV projection: N = 1536; Q,K row-major; V transposed
        gemm_k<128,128,3,false><<<dim3(12, 32), 128, S128>>>(
            xh, xl, DMODEL, wqkvTh + qoff, wqkvTl + qoff, DMODEL,
            nullptr, qh, ql, kh, kl, vTh, vTl, DMODEL,
            bqkv + (long long)i * NQKV, 1.f, DMODEL);

        // fused attention -> bf16 hi/lo attn in bugged layout
        flash_k<<<dim3(16, 32), 128, FSMEM>>>(qh, ql, kh, kl, vTh, vTl, ah, al);

        // O projection -> fp32 y
        gemm_k<128,128,0,false><<<dim3(4, 32), 128, S128>>>(
            ah, al, DMODEL, woTh + woff, woTl + woff, DMODEL,
            y, nullptr, nullptr, nullptr, nullptr, nullptr, nullptr, DMODEL,
            boi, 1.f, DMODEL);

        addln_k<true><<<TOKENS, 128>>>(x, y, lgi, lbi, x, xh, xl);

        // FFN1 (relu) -> bf16 hi/lo [4096][2048]
        gemm_k<128,128,1,true><<<dim3(16, 32), 128, S128>>>(
            xh, xl, DMODEL, w1Th + foff, w1Tl + foff, DMODEL,
            nullptr, h1h, h1l, nullptr, nullptr, nullptr, nullptr, DFF,
            b1i, 1.f, DMODEL);

        // FFN2 -> fp32 y
        gemm_k<128,128,0,false><<<dim3(4, 32), 128, S128>>>(
            h1h, h1l, DFF, w2Th + foff, w2Tl + foff, DFF,
            y, nullptr, nullptr, nullptr, nullptr, nullptr, nullptr, DMODEL,
            b2i, 1.f, DFF);

        if (i == NLAYERS - 1)
            addln_k<false><<<TOKENS, 128>>>(x, y, lgi, lbi, out, nullptr, nullptr);
        else
            addln_k<true><<<TOKENS, 128>>>(x, y, lgi, lbi, x, xh, xl);
    }
}